// round 13
// baseline (speedup 1.0000x reference)
#include <cuda_runtime.h>
#include <cuda_fp16.h>
#include <cstdint>

typedef unsigned long long u64;
typedef unsigned u32;

// ===== per-point separable layer0 tables =====
// A tables: PERMUTED per-point: index point*32 + cc*8 + nt*2 + e  (c = 8nt+2cc+e)
// B tables: warp-coalesced: [jblock=j>>3][c4][lane=(j&7)*4+cc][q]  (perm off cc*8+c4*4+q)
__device__ float g_A0[1024 * 32];
__device__ float g_B0[1024 * 32];
__device__ float g_A1[1024 * 32];
__device__ float g_B1[1024 * 32];

// ================= weight B-fragments (single fp16) =================
#define T_L0W2  0    // 2kt x 4nt
#define T_L1W1  8
#define T_L1W2  16
#define T_L2W0  24   // 2kt x 2nt
#define T_L2W1  28
#define T_L2W2  32   // 1kt x 2nt
#define T_FW    34   // 1kt x 9nt (N=66 pad 72)
#define N_TILES 43

__device__ u64 g_frag[N_TILES * 32];

__device__ __forceinline__ u32 h16b(float v) {
    return (u32)__half_as_ushort(__float2half_rn(v));
}

// ---- fused prep: blocks [0,256) = per-point tables; blocks [256,267) = frags ----
__global__ void prep(const float* __restrict__ feat,
                     const float* __restrict__ w0, const float* __restrict__ b0,
                     const float* __restrict__ w1, const float* __restrict__ b1,
                     const float* __restrict__ l0w2, const float* __restrict__ l1w1,
                     const float* __restrict__ l1w2, const float* __restrict__ l2w0,
                     const float* __restrict__ l2w1, const float* __restrict__ l2w2,
                     const float* __restrict__ fw) {
    int b = blockIdx.x;
    if (b < 256) {
        int t = b * 256 + threadIdx.x;          // 65536 threads
        int i = t >> 6, rem = t & 63, sel = rem >> 5, c = rem & 31;
        const float* f = feat + i * 40;
        const float* w = sel ? w1 : w0;
        float a = sel ? b1[c] : b0[c], bo = 0.f;
#pragma unroll
        for (int k = 0; k < 40; k++) {
            float fv = f[k];
            a  = fmaf(fv, w[k * 32 + c],        a);
            bo = fmaf(fv, w[(k + 40) * 32 + c], bo);
        }
        // permuted index: c = 8*nt + 2*cc + e  ->  p = cc*8 + nt*2 + e
        int p = ((c & 7) >> 1) * 8 + (c >> 3) * 2 + (c & 1);
        // B-table coalesced index
        int jblock = i >> 3, rr = i & 7;
        int ccp = p >> 3, c4p = (p >> 2) & 1, q = p & 3;
        int nb = jblock * 256 + c4p * 128 + (rr * 4 + ccp) * 4 + q;
        if (sel) { g_A1[i * 32 + p] = a; g_B1[nb] = bo; }
        else     { g_A0[i * 32 + p] = a; g_B0[nb] = bo; }
    } else {
        int e = (b - 256) * 256 + threadIdx.x;
        if (e >= N_TILES * 32) return;
        struct Spec { const float* w; int K, N, nnt, base, ntiles; };
        Spec sp[7] = {
            {l0w2, 32, 32, 4, T_L0W2, 8},
            {l1w1, 32, 32, 4, T_L1W1, 8},
            {l1w2, 32, 32, 4, T_L1W2, 8},
            {l2w0, 32, 16, 2, T_L2W0, 4},
            {l2w1, 32, 16, 2, T_L2W1, 4},
            {l2w2, 16, 16, 2, T_L2W2, 2},
            {fw,   16, 66, 9, T_FW,   9},
        };
        int tile = e >> 5, lane = e & 31;
        int si = 0;
        for (int q = 0; q < 7; q++)
            if (tile >= sp[q].base && tile < sp[q].base + sp[q].ntiles) si = q;
        const float* w = sp[si].w;
        int K = sp[si].K, N = sp[si].N, nnt = sp[si].nnt;
        int lt = tile - sp[si].base, kt = lt / nnt, nt = lt % nnt;
        int n = nt * 8 + (lane >> 2), cc = lane & 3;
        int ks[4] = {kt * 16 + 2 * cc, kt * 16 + 2 * cc + 1,
                     kt * 16 + 2 * cc + 8, kt * 16 + 2 * cc + 9};
        u32 bits[4];
#pragma unroll
        for (int q = 0; q < 4; q++) {
            int k = ks[q];
            float v = (k < K && n < N) ? w[k * N + n] : 0.f;
            bits[q] = h16b(v);
        }
        u32 lo = (bits[1] << 16) | bits[0];
        u32 hi = (bits[3] << 16) | bits[2];
        g_frag[e] = ((u64)hi << 32) | (u64)lo;
    }
}

// ================= MMA helpers (fp16 in, fp32 acc) =================
__device__ __forceinline__ void mma_acc(float c[4], const u32 a[4], u64 b) {
    u32 b0 = (u32)b, b1 = (u32)(b >> 32);
    asm volatile("mma.sync.aligned.m16n8k16.row.col.f32.f16.f16.f32 "
        "{%0,%1,%2,%3}, {%4,%5,%6,%7}, {%8,%9}, {%0,%1,%2,%3};"
        : "+f"(c[0]), "+f"(c[1]), "+f"(c[2]), "+f"(c[3])
        : "r"(a[0]), "r"(a[1]), "r"(a[2]), "r"(a[3]), "r"(b0), "r"(b1));
}
__device__ __forceinline__ void mma2(float c[4], const u32 ah[4], const u32 al[4], u64 w) {
    mma_acc(c, ah, w);
    mma_acc(c, al, w);
}

// pack (x0 low, x1 high) into fp16x2 hi, residue into lo
__device__ __forceinline__ void split2(float x0, float x1, u32& hi, u32& lo) {
    __half2 h = __floats2half2_rn(x0, x1);
    float2 f = __half22float2(h);
    __half2 l = __floats2half2_rn(x0 - f.x, x1 - f.y);
    hi = *reinterpret_cast<u32*>(&h);
    lo = *reinterpret_cast<u32*>(&l);
}
__device__ __forceinline__ u32 split2h(float x0, float x1) {
    __half2 h = __floats2half2_rn(x0, x1);
    return *reinterpret_cast<u32*>(&h);
}
__device__ __forceinline__ float2 h2f(u32 v) {
    __half2 h = *reinterpret_cast<__half2*>(&v);
    return __half22float2(h);
}

// D tiles (ntile 2kt, 2kt+1) -> A frag (ktile kt), hi+lo, optional relu
template<bool RELU>
__device__ __forceinline__ void d2a(const float* d0, const float* d1, u32* ah, u32* al) {
    float v0 = d0[0], v1 = d0[1], v2 = d0[2], v3 = d0[3];
    float w0 = d1[0], w1 = d1[1], w2 = d1[2], w3 = d1[3];
    if (RELU) {
        v0 = fmaxf(v0, 0.f); v1 = fmaxf(v1, 0.f); v2 = fmaxf(v2, 0.f); v3 = fmaxf(v3, 0.f);
        w0 = fmaxf(w0, 0.f); w1 = fmaxf(w1, 0.f); w2 = fmaxf(w2, 0.f); w3 = fmaxf(w3, 0.f);
    }
    split2(v0, v1, ah[0], al[0]);
    split2(v2, v3, ah[1], al[1]);
    split2(w0, w1, ah[2], al[2]);
    split2(w2, w3, ah[3], al[3]);
}
// hi-only A frag, optional relu
template<bool RELU>
__device__ __forceinline__ void d2a_h(const float* d0, const float* d1, u32* ah) {
    float v0 = d0[0], v1 = d0[1], v2 = d0[2], v3 = d0[3];
    float w0 = d1[0], w1 = d1[1], w2 = d1[2], w3 = d1[3];
    if (RELU) {
        v0 = fmaxf(v0, 0.f); v1 = fmaxf(v1, 0.f); v2 = fmaxf(v2, 0.f); v3 = fmaxf(v3, 0.f);
        w0 = fmaxf(w0, 0.f); w1 = fmaxf(w1, 0.f); w2 = fmaxf(w2, 0.f); w3 = fmaxf(w3, 0.f);
    }
    ah[0] = split2h(v0, v1);
    ah[1] = split2h(v2, v3);
    ah[2] = split2h(w0, w1);
    ah[3] = split2h(w2, w3);
}

#define SOUT_STRIDE 74   // 74 mod 32 = 10 -> conflict-free row stagger, float2-aligned

// ====== main kernel: warp = 32 pairs, tiled 4i x 8j; NO block-level syncs ======
__global__ void __launch_bounds__(128, 4) ppf_main(
    const float* __restrict__ pc, const float* __restrict__ nrm,
    const float* __restrict__ dist,
    const float* __restrict__ fc0w, const float* __restrict__ fc1w,
    const float* __restrict__ l0b2, const float* __restrict__ l1b1,
    const float* __restrict__ l1b2, const float* __restrict__ l2b0,
    const float* __restrict__ l2b1, const float* __restrict__ l2b2,
    const float* __restrict__ fb, float* __restrict__ out)
{
    __shared__ float sout[4][32][SOUT_STRIDE];
    const int tid = threadIdx.x;
    const int lane = tid & 31, warp = tid >> 5;
    const int bx = blockIdx.x;
    const int ib = (bx >> 5) << 2;                    // 4 i's per CTA
    const int jb8 = ((bx & 31) << 5) + (warp << 3);   // 8 j's per warp
    const int r = lane >> 2, cc = lane & 3;
    const int col0 = 2 * cc;
    const int jr = jb8 + r;

    // ---- per-lane PPF: 4 pairs (ib+q, jr); q=2mt+half; half0->pA[mt], half1->pB[mt]
    float pA[2][4], pB[2][4];
    {
        float pcjx = pc[3 * jr], pcjy = pc[3 * jr + 1], pcjz = pc[3 * jr + 2];
        float njx = nrm[3 * jr], njy = nrm[3 * jr + 1], njz = nrm[3 * jr + 2];
#pragma unroll
        for (int q = 0; q < 4; q++) {
            int i = ib + q;
            float pcix = pc[3 * i], pciy = pc[3 * i + 1], pciz = pc[3 * i + 2];
            float nix = nrm[3 * i], niy = nrm[3 * i + 1], niz = nrm[3 * i + 2];
            float dd = dist[(i << 10) + jr];
            float inv = 1.0f / (dd + 1e-7f);
            float xx0 = pcix - pcjx, xx1 = pciy - pcjy, xx2 = pciz - pcjz;
            float p0 = (nix * xx0 + niy * xx1 + niz * xx2) * inv;
            float p1 = (njx * xx0 + njy * xx1 + njz * xx2) * inv;
            float p2 = nix * njx + niy * njy + niz * njz;
            float* dstp = (q & 1) ? pB[q >> 1] : pA[q >> 1];
            dstp[0] = p0; dstp[1] = p1; dstp[2] = p2; dstp[3] = dd;
        }
    }

    const int tb = (cc << 3);             // A-table perm base for this cc
    const int jbl = (jb8 >> 3) * 256;     // B-table coalesced block base

    // ---- layer0: X1 = relu(A1[i] + B1[j] + ppf@W1p) ----
    float cx[2][4][4];
#pragma unroll
    for (int c4 = 0; c4 < 2; c4++) {
        float4 bv = *(const float4*)(g_B1 + jbl + c4 * 128 + lane * 4);
        float4 a0v = ((const float4*)(g_A1 + ((ib + 0) << 5) + tb))[c4];
        float4 a1v = ((const float4*)(g_A1 + ((ib + 1) << 5) + tb))[c4];
        float4 a2v = ((const float4*)(g_A1 + ((ib + 2) << 5) + tb))[c4];
        float4 a3v = ((const float4*)(g_A1 + ((ib + 3) << 5) + tb))[c4];
#pragma unroll
        for (int h = 0; h < 2; h++) {
            int nt = 2 * c4 + h;
            int col = 8 * nt + col0;
            float bxv = h ? bv.z : bv.x, byv = h ? bv.w : bv.y;
            cx[0][nt][0] = (h ? a0v.z : a0v.x) + bxv; cx[0][nt][1] = (h ? a0v.w : a0v.y) + byv;
            cx[0][nt][2] = (h ? a1v.z : a1v.x) + bxv; cx[0][nt][3] = (h ? a1v.w : a1v.y) + byv;
            cx[1][nt][0] = (h ? a2v.z : a2v.x) + bxv; cx[1][nt][1] = (h ? a2v.w : a2v.y) + byv;
            cx[1][nt][2] = (h ? a3v.z : a3v.x) + bxv; cx[1][nt][3] = (h ? a3v.w : a3v.y) + byv;
#pragma unroll
            for (int k = 0; k < 4; k++) {
                float2 wv = *(const float2*)(fc1w + 80 * 32 + k * 32 + col);
                cx[0][nt][0] = fmaf(pA[0][k], wv.x, cx[0][nt][0]);
                cx[0][nt][1] = fmaf(pA[0][k], wv.y, cx[0][nt][1]);
                cx[0][nt][2] = fmaf(pB[0][k], wv.x, cx[0][nt][2]);
                cx[0][nt][3] = fmaf(pB[0][k], wv.y, cx[0][nt][3]);
                cx[1][nt][0] = fmaf(pA[1][k], wv.x, cx[1][nt][0]);
                cx[1][nt][1] = fmaf(pA[1][k], wv.y, cx[1][nt][1]);
                cx[1][nt][2] = fmaf(pB[1][k], wv.x, cx[1][nt][2]);
                cx[1][nt][3] = fmaf(pB[1][k], wv.y, cx[1][nt][3]);
            }
        }
    }
    // X1 hi-only
    u32 x1h[2][2][4];
#pragma unroll
    for (int mt = 0; mt < 2; mt++)
#pragma unroll
        for (int kt = 0; kt < 2; kt++)
            d2a_h<true>(cx[mt][2 * kt], cx[mt][2 * kt + 1], x1h[mt][kt]);

    // ---- residual R0 = A0[i] + B0[j] + ppf@W0p  (reuse cx) ----
#pragma unroll
    for (int c4 = 0; c4 < 2; c4++) {
        float4 bv = *(const float4*)(g_B0 + jbl + c4 * 128 + lane * 4);
        float4 a0v = ((const float4*)(g_A0 + ((ib + 0) << 5) + tb))[c4];
        float4 a1v = ((const float4*)(g_A0 + ((ib + 1) << 5) + tb))[c4];
        float4 a2v = ((const float4*)(g_A0 + ((ib + 2) << 5) + tb))[c4];
        float4 a3v = ((const float4*)(g_A0 + ((ib + 3) << 5) + tb))[c4];
#pragma unroll
        for (int h = 0; h < 2; h++) {
            int nt = 2 * c4 + h;
            int col = 8 * nt + col0;
            float bxv = h ? bv.z : bv.x, byv = h ? bv.w : bv.y;
            cx[0][nt][0] = (h ? a0v.z : a0v.x) + bxv; cx[0][nt][1] = (h ? a0v.w : a0v.y) + byv;
            cx[0][nt][2] = (h ? a1v.z : a1v.x) + bxv; cx[0][nt][3] = (h ? a1v.w : a1v.y) + byv;
            cx[1][nt][0] = (h ? a2v.z : a2v.x) + bxv; cx[1][nt][1] = (h ? a2v.w : a2v.y) + byv;
            cx[1][nt][2] = (h ? a3v.z : a3v.x) + bxv; cx[1][nt][3] = (h ? a3v.w : a3v.y) + byv;
#pragma unroll
            for (int k = 0; k < 4; k++) {
                float2 wv = *(const float2*)(fc0w + 80 * 32 + k * 32 + col);
                cx[0][nt][0] = fmaf(pA[0][k], wv.x, cx[0][nt][0]);
                cx[0][nt][1] = fmaf(pA[0][k], wv.y, cx[0][nt][1]);
                cx[0][nt][2] = fmaf(pB[0][k], wv.x, cx[0][nt][2]);
                cx[0][nt][3] = fmaf(pB[0][k], wv.y, cx[0][nt][3]);
                cx[1][nt][0] = fmaf(pA[1][k], wv.x, cx[1][nt][0]);
                cx[1][nt][1] = fmaf(pA[1][k], wv.y, cx[1][nt][1]);
                cx[1][nt][2] = fmaf(pB[1][k], wv.x, cx[1][nt][2]);
                cx[1][nt][3] = fmaf(pB[1][k], wv.y, cx[1][nt][3]);
            }
        }
    }

    // ---- l0fc2: X2 = X1@W2 + b2 + R0  (hi-only A) ----
#pragma unroll
    for (int nt = 0; nt < 4; nt++) {
        float2 bv = *(const float2*)(l0b2 + 8 * nt + col0);
#pragma unroll
        for (int mt = 0; mt < 2; mt++) {
            cx[mt][nt][0] += bv.x; cx[mt][nt][1] += bv.y;
            cx[mt][nt][2] += bv.x; cx[mt][nt][3] += bv.y;
        }
    }
#pragma unroll
    for (int kt = 0; kt < 2; kt++)
#pragma unroll
        for (int nt = 0; nt < 4; nt++) {
            u64 wv = g_frag[(T_L0W2 + kt * 4 + nt) * 32 + lane];
            mma_acc(cx[0][nt], x1h[0][kt], wv);
            mma_acc(cx[1][nt], x1h[1][kt], wv);
        }
    u32 x2h[2][2][4], x2l[2][2][4];
#pragma unroll
    for (int mt = 0; mt < 2; mt++)
#pragma unroll
        for (int kt = 0; kt < 2; kt++)
            d2a<false>(cx[mt][2 * kt], cx[mt][2 * kt + 1], x2h[mt][kt], x2l[mt][kt]);

    // ---- layer1 fc1: H = relu(X2@W1 + b1) -- accumulate in cx ----
#pragma unroll
    for (int nt = 0; nt < 4; nt++) {
        float2 bv = *(const float2*)(l1b1 + 8 * nt + col0);
#pragma unroll
        for (int mt = 0; mt < 2; mt++) {
            cx[mt][nt][0] = bv.x; cx[mt][nt][1] = bv.y;
            cx[mt][nt][2] = bv.x; cx[mt][nt][3] = bv.y;
        }
    }
#pragma unroll
    for (int kt = 0; kt < 2; kt++)
#pragma unroll
        for (int nt = 0; nt < 4; nt++) {
            u64 wv = g_frag[(T_L1W1 + kt * 4 + nt) * 32 + lane];
            mma2(cx[0][nt], x2h[0][kt], x2l[0][kt], wv);
            mma2(cx[1][nt], x2h[1][kt], x2l[1][kt], wv);
        }
    u32 hh[2][2][4];
#pragma unroll
    for (int mt = 0; mt < 2; mt++)
#pragma unroll
        for (int kt = 0; kt < 2; kt++)
            d2a_h<true>(cx[mt][2 * kt], cx[mt][2 * kt + 1], hh[mt][kt]);

    // ---- layer1 fc2: X3 = H@W2 + b2 + X2 (X2 reconstructed from x2h + x2l) ----
#pragma unroll
    for (int kt = 0; kt < 2; kt++)
#pragma unroll
        for (int h = 0; h < 2; h++) {
            int nt = 2 * kt + h;
            float2 bv = *(const float2*)(l1b2 + 8 * nt + col0);
#pragma unroll
            for (int mt = 0; mt < 2; mt++) {
                float2 hA = h2f(x2h[mt][kt][2 * h]),     lA = h2f(x2l[mt][kt][2 * h]);
                float2 hB = h2f(x2h[mt][kt][2 * h + 1]), lB = h2f(x2l[mt][kt][2 * h + 1]);
                cx[mt][nt][0] = bv.x + hA.x + lA.x;
                cx[mt][nt][1] = bv.y + hA.y + lA.y;
                cx[mt][nt][2] = bv.x + hB.x + lB.x;
                cx[mt][nt][3] = bv.y + hB.y + lB.y;
            }
        }
#pragma unroll
    for (int kt = 0; kt < 2; kt++)
#pragma unroll
        for (int nt = 0; nt < 4; nt++) {
            u64 wv = g_frag[(T_L1W2 + kt * 4 + nt) * 32 + lane];
            mma_acc(cx[0][nt], hh[0][kt], wv);
            mma_acc(cx[1][nt], hh[1][kt], wv);
        }
    // X3 hi-only
    u32 x3h[2][2][4];
#pragma unroll
    for (int mt = 0; mt < 2; mt++)
#pragma unroll
        for (int kt = 0; kt < 2; kt++)
            d2a_h<false>(cx[mt][2 * kt], cx[mt][2 * kt + 1], x3h[mt][kt]);

    // ---- layer2 ----
    float ca[2][2][4], cb[2][2][4];
#pragma unroll
    for (int nt = 0; nt < 2; nt++) {
        float2 b0v = *(const float2*)(l2b0 + 8 * nt + col0);
        float2 b1v = *(const float2*)(l2b1 + 8 * nt + col0);
#pragma unroll
        for (int mt = 0; mt < 2; mt++) {
            ca[mt][nt][0] = b0v.x; ca[mt][nt][1] = b0v.y;
            ca[mt][nt][2] = b0v.x; ca[mt][nt][3] = b0v.y;
            cb[mt][nt][0] = b1v.x; cb[mt][nt][1] = b1v.y;
            cb[mt][nt][2] = b1v.x; cb[mt][nt][3] = b1v.y;
        }
    }
#pragma unroll
    for (int kt = 0; kt < 2; kt++)
#pragma unroll
        for (int nt = 0; nt < 2; nt++) {
            u64 w0v = g_frag[(T_L2W0 + kt * 2 + nt) * 32 + lane];
            u64 w1v = g_frag[(T_L2W1 + kt * 2 + nt) * 32 + lane];
#pragma unroll
            for (int mt = 0; mt < 2; mt++) {
                mma_acc(ca[mt][nt], x3h[mt][kt], w0v);
                mma_acc(cb[mt][nt], x3h[mt][kt], w1v);
            }
        }
    u32 h2h[2][4];
#pragma unroll
    for (int mt = 0; mt < 2; mt++) d2a_h<true>(cb[mt][0], cb[mt][1], h2h[mt]);
#pragma unroll
    for (int nt = 0; nt < 2; nt++) {
        float2 bv = *(const float2*)(l2b2 + 8 * nt + col0);
        u64 wv = g_frag[(T_L2W2 + nt) * 32 + lane];
#pragma unroll
        for (int mt = 0; mt < 2; mt++) {
            ca[mt][nt][0] += bv.x; ca[mt][nt][1] += bv.y;
            ca[mt][nt][2] += bv.x; ca[mt][nt][3] += bv.y;
            mma_acc(ca[mt][nt], h2h[mt], wv);
        }
    }
    // X4 hi-only
    u32 x4h[2][4];
#pragma unroll
    for (int mt = 0; mt < 2; mt++) d2a_h<false>(ca[mt][0], ca[mt][1], x4h[mt]);

    // ---- final: OUT = X4 @ fw + fb -> stage in smem (row s = i_loc*8 + j_loc) ----
#pragma unroll
    for (int nt = 0; nt < 9; nt++) {
        int col = 8 * nt + col0;
        bool valid = (col < 66);
        float2 bv = valid ? *(const float2*)(fb + col) : make_float2(0.f, 0.f);
        u64 wv = g_frag[(T_FW + nt) * 32 + lane];
#pragma unroll
        for (int mt = 0; mt < 2; mt++) {
            float cf[4] = {bv.x, bv.y, bv.x, bv.y};
            mma_acc(cf, x4h[mt], wv);
            *(float2*)&sout[warp][(2 * mt) * 8 + r][col]     = make_float2(cf[0], cf[1]);
            *(float2*)&sout[warp][(2 * mt + 1) * 8 + r][col] = make_float2(cf[2], cf[3]);
        }
    }
    __syncwarp();
    // dense copy, division-free: per i-block, 8 full-width float2 rows + 8-lane tail
    {
        const float* src = &sout[warp][0][0];
#pragma unroll
        for (int blk = 0; blk < 4; blk++) {
            float* dst = out + (((size_t)(ib + blk) << 10) + (size_t)jb8) * 66ull;
#pragma unroll
            for (int row = 0; row < 8; row++) {
                float2 v = *(const float2*)(src + (blk * 8 + row) * SOUT_STRIDE + 2 * lane);
                *(float2*)(dst + row * 66 + 2 * lane) = v;
            }
            if (lane < 8) {
                float2 v = *(const float2*)(src + (blk * 8 + lane) * SOUT_STRIDE + 64);
                *(float2*)(dst + lane * 66 + 64) = v;
            }
        }
    }
}

extern "C" void kernel_launch(void* const* d_in, const int* in_sizes, int n_in,
                              void* d_out, int out_size) {
    const float* pc   = (const float*)d_in[0];
    const float* nrm  = (const float*)d_in[1];
    const float* dist = (const float*)d_in[2];
    const float* feat = (const float*)d_in[3];
    const float* w0   = (const float*)d_in[4];   const float* b0   = (const float*)d_in[5];
    const float* w1   = (const float*)d_in[6];   const float* b1   = (const float*)d_in[7];
    const float* l0w2 = (const float*)d_in[8];   const float* l0b2 = (const float*)d_in[9];
    const float* l1w1 = (const float*)d_in[10];  const float* l1b1 = (const float*)d_in[11];
    const float* l1w2 = (const float*)d_in[12];  const float* l1b2 = (const float*)d_in[13];
    const float* l2w0 = (const float*)d_in[14];  const float* l2b0 = (const float*)d_in[15];
    const float* l2w1 = (const float*)d_in[16];  const float* l2b1 = (const float*)d_in[17];
    const float* l2w2 = (const float*)d_in[18];  const float* l2b2 = (const float*)d_in[19];
    const float* fw   = (const float*)d_in[20];  const float* fb   = (const float*)d_in[21];
    float* out = (float*)d_out;

    prep<<<267, 256>>>(feat, w0, b0, w1, b1,
                       l0w2, l1w1, l1w2, l2w0, l2w1, l2w2, fw);
    ppf_main<<<8192, 128>>>(pc, nrm, dist, w0, w1,
                            l0b2, l1b1, l1b2, l2b0, l2b1, l2b2, fb, out);
}

// round 14
// speedup vs baseline: 1.1561x; 1.1561x over previous
#include <cuda_runtime.h>
#include <cuda_fp16.h>
#include <cstdint>

typedef unsigned long long u64;
typedef unsigned u32;

// ===== per-point separable layer0 tables =====
// A tables: PERMUTED per-point: index point*32 + cc*8 + nt*2 + e  (c = 8nt+2cc+e)
// B tables: warp-coalesced: [jblock=j>>3][c4][(j&7)*4+cc][q]  (perm p = cc*8+c4*4+q)
__device__ float g_A0[1024 * 32];
__device__ float g_B0[1024 * 32];
__device__ float g_A1[1024 * 32];
__device__ float g_B1[1024 * 32];

// ================= weight B-fragments (single fp16) =================
#define T_L0W2  0    // 2kt x 4nt
#define T_L1W1  8
#define T_L1W2  16
#define T_L2W0  24   // 2kt x 2nt
#define T_L2W1  28
#define T_L2W2  32   // 1kt x 2nt
#define T_FW    34   // 1kt x 9nt (N=66 pad 72)
#define N_TILES 43

__device__ u64 g_frag[N_TILES * 32];

__device__ __forceinline__ u32 h16b(float v) {
    return (u32)__half_as_ushort(__float2half_rn(v));
}

// ---- fused prep: blocks [0,256) = per-point tables; blocks [256,267) = frags ----
__global__ void prep(const float* __restrict__ feat,
                     const float* __restrict__ w0, const float* __restrict__ b0,
                     const float* __restrict__ w1, const float* __restrict__ b1,
                     const float* __restrict__ l0w2, const float* __restrict__ l1w1,
                     const float* __restrict__ l1w2, const float* __restrict__ l2w0,
                     const float* __restrict__ l2w1, const float* __restrict__ l2w2,
                     const float* __restrict__ fw) {
    int b = blockIdx.x;
    if (b < 256) {
        int t = b * 256 + threadIdx.x;          // 65536 threads
        int i = t >> 6, rem = t & 63, sel = rem >> 5, c = rem & 31;
        const float* f = feat + i * 40;
        const float* w = sel ? w1 : w0;
        float a = sel ? b1[c] : b0[c], bo = 0.f;
#pragma unroll
        for (int k = 0; k < 40; k++) {
            float fv = f[k];
            a  = fmaf(fv, w[k * 32 + c],        a);
            bo = fmaf(fv, w[(k + 40) * 32 + c], bo);
        }
        // permuted index: c = 8*nt + 2*cc + e  ->  p = cc*8 + nt*2 + e
        int p = ((c & 7) >> 1) * 8 + (c >> 3) * 2 + (c & 1);
        // B-table coalesced index
        int jblock = i >> 3, rr = i & 7;
        int ccp = p >> 3, c4p = (p >> 2) & 1, q = p & 3;
        int nb = jblock * 256 + c4p * 128 + (rr * 4 + ccp) * 4 + q;
        if (sel) { g_A1[i * 32 + p] = a; g_B1[nb] = bo; }
        else     { g_A0[i * 32 + p] = a; g_B0[nb] = bo; }
    } else {
        int e = (b - 256) * 256 + threadIdx.x;
        if (e >= N_TILES * 32) return;
        struct Spec { const float* w; int K, N, nnt, base, ntiles; };
        Spec sp[7] = {
            {l0w2, 32, 32, 4, T_L0W2, 8},
            {l1w1, 32, 32, 4, T_L1W1, 8},
            {l1w2, 32, 32, 4, T_L1W2, 8},
            {l2w0, 32, 16, 2, T_L2W0, 4},
            {l2w1, 32, 16, 2, T_L2W1, 4},
            {l2w2, 16, 16, 2, T_L2W2, 2},
            {fw,   16, 66, 9, T_FW,   9},
        };
        int tile = e >> 5, lane = e & 31;
        int si = 0;
        for (int q = 0; q < 7; q++)
            if (tile >= sp[q].base && tile < sp[q].base + sp[q].ntiles) si = q;
        const float* w = sp[si].w;
        int K = sp[si].K, N = sp[si].N, nnt = sp[si].nnt;
        int lt = tile - sp[si].base, kt = lt / nnt, nt = lt % nnt;
        int n = nt * 8 + (lane >> 2), cc = lane & 3;
        int ks[4] = {kt * 16 + 2 * cc, kt * 16 + 2 * cc + 1,
                     kt * 16 + 2 * cc + 8, kt * 16 + 2 * cc + 9};
        u32 bits[4];
#pragma unroll
        for (int q = 0; q < 4; q++) {
            int k = ks[q];
            float v = (k < K && n < N) ? w[k * N + n] : 0.f;
            bits[q] = h16b(v);
        }
        u32 lo = (bits[1] << 16) | bits[0];
        u32 hi = (bits[3] << 16) | bits[2];
        g_frag[e] = ((u64)hi << 32) | (u64)lo;
    }
}

// ================= MMA helpers (fp16 in, fp32 acc) =================
__device__ __forceinline__ void mma_acc(float c[4], const u32 a[4], u64 b) {
    u32 b0 = (u32)b, b1 = (u32)(b >> 32);
    asm volatile("mma.sync.aligned.m16n8k16.row.col.f32.f16.f16.f32 "
        "{%0,%1,%2,%3}, {%4,%5,%6,%7}, {%8,%9}, {%0,%1,%2,%3};"
        : "+f"(c[0]), "+f"(c[1]), "+f"(c[2]), "+f"(c[3])
        : "r"(a[0]), "r"(a[1]), "r"(a[2]), "r"(a[3]), "r"(b0), "r"(b1));
}
__device__ __forceinline__ void mma2(float c[4], const u32 ah[4], const u32 al[4], u64 w) {
    mma_acc(c, ah, w);
    mma_acc(c, al, w);
}

// pack (x0 low, x1 high) into fp16x2 hi, residue into lo
__device__ __forceinline__ void split2(float x0, float x1, u32& hi, u32& lo) {
    __half2 h = __floats2half2_rn(x0, x1);
    float2 f = __half22float2(h);
    __half2 l = __floats2half2_rn(x0 - f.x, x1 - f.y);
    hi = *reinterpret_cast<u32*>(&h);
    lo = *reinterpret_cast<u32*>(&l);
}
__device__ __forceinline__ u32 split2h(float x0, float x1) {
    __half2 h = __floats2half2_rn(x0, x1);
    return *reinterpret_cast<u32*>(&h);
}
__device__ __forceinline__ float2 h2f(u32 v) {
    __half2 h = *reinterpret_cast<__half2*>(&v);
    return __half22float2(h);
}

// D tiles (ntile 2kt, 2kt+1) -> A frag (ktile kt), hi+lo, optional relu
template<bool RELU>
__device__ __forceinline__ void d2a(const float* d0, const float* d1, u32* ah, u32* al) {
    float v0 = d0[0], v1 = d0[1], v2 = d0[2], v3 = d0[3];
    float w0 = d1[0], w1 = d1[1], w2 = d1[2], w3 = d1[3];
    if (RELU) {
        v0 = fmaxf(v0, 0.f); v1 = fmaxf(v1, 0.f); v2 = fmaxf(v2, 0.f); v3 = fmaxf(v3, 0.f);
        w0 = fmaxf(w0, 0.f); w1 = fmaxf(w1, 0.f); w2 = fmaxf(w2, 0.f); w3 = fmaxf(w3, 0.f);
    }
    split2(v0, v1, ah[0], al[0]);
    split2(v2, v3, ah[1], al[1]);
    split2(w0, w1, ah[2], al[2]);
    split2(w2, w3, ah[3], al[3]);
}
// hi-only A frag, optional relu
template<bool RELU>
__device__ __forceinline__ void d2a_h(const float* d0, const float* d1, u32* ah) {
    float v0 = d0[0], v1 = d0[1], v2 = d0[2], v3 = d0[3];
    float w0 = d1[0], w1 = d1[1], w2 = d1[2], w3 = d1[3];
    if (RELU) {
        v0 = fmaxf(v0, 0.f); v1 = fmaxf(v1, 0.f); v2 = fmaxf(v2, 0.f); v3 = fmaxf(v3, 0.f);
        w0 = fmaxf(w0, 0.f); w1 = fmaxf(w1, 0.f); w2 = fmaxf(w2, 0.f); w3 = fmaxf(w3, 0.f);
    }
    ah[0] = split2h(v0, v1);
    ah[1] = split2h(v2, v3);
    ah[2] = split2h(w0, w1);
    ah[3] = split2h(w2, w3);
}

#define SOUT_STRIDE 74   // 74 mod 32 = 10 -> conflict-free row stagger, float2-aligned

// ====== main kernel: warp = 32 pairs, tiled 4i x 8j (two m16 tiles of 2i x 8j) ======
__global__ void __launch_bounds__(128, 4) ppf_main(
    const float* __restrict__ pc, const float* __restrict__ nrm,
    const float* __restrict__ dist,
    const float* __restrict__ fc0w, const float* __restrict__ fc1w,
    const float* __restrict__ l0b2, const float* __restrict__ l1b1,
    const float* __restrict__ l1b2, const float* __restrict__ l2b0,
    const float* __restrict__ l2b1, const float* __restrict__ l2b2,
    const float* __restrict__ fb, float* __restrict__ out)
{
    __shared__ float sppf[4][32][4];
    __shared__ float sW1p[4][32];
    __shared__ float sW0p[4][32];
    __shared__ float sout[4][32][SOUT_STRIDE];
    const int tid = threadIdx.x;
    const int lane = tid & 31, warp = tid >> 5;
    const int bx = blockIdx.x;
    const int ib = (bx >> 5) << 2;                    // 4 i's per CTA
    const int jb8 = ((bx & 31) << 5) + (warp << 3);   // 8 j's per warp
    const int r = lane >> 2, cc = lane & 3;
    const int col0 = 2 * cc;

    // stage ppf-weight rows (80..83) of fc1/fc0
    if (tid < 128) {
        sW1p[tid >> 5][tid & 31] = fc1w[80 * 32 + tid];
        sW0p[tid >> 5][tid & 31] = fc0w[80 * 32 + tid];
    }

    // ---- PPF features: lane = i_loc*8 + j_loc ----
    {
        int i = ib + (lane >> 3);
        int j = jb8 + (lane & 7);
        float pcix = pc[3 * i], pciy = pc[3 * i + 1], pciz = pc[3 * i + 2];
        float nix = nrm[3 * i], niy = nrm[3 * i + 1], niz = nrm[3 * i + 2];
        float pcjx = pc[3 * j], pcjy = pc[3 * j + 1], pcjz = pc[3 * j + 2];
        float njx = nrm[3 * j], njy = nrm[3 * j + 1], njz = nrm[3 * j + 2];
        float dd = dist[(i << 10) + j];
        float inv = 1.0f / (dd + 1e-7f);
        float xx0 = pcix - pcjx, xx1 = pciy - pcjy, xx2 = pciz - pcjz;
        sppf[warp][lane][0] = (nix * xx0 + niy * xx1 + niz * xx2) * inv;
        sppf[warp][lane][1] = (njx * xx0 + njy * xx1 + njz * xx2) * inv;
        sppf[warp][lane][2] = nix * njx + niy * njy + niz * njz;
        sppf[warp][lane][3] = dd;
    }
    __syncthreads();

    // ppf rows this lane needs: pA -> row r (pair (ib+2mt, jb8+r)), pB -> row r+8
    float pA[2][4], pB[2][4];
#pragma unroll
    for (int mt = 0; mt < 2; mt++)
#pragma unroll
        for (int k = 0; k < 4; k++) {
            pA[mt][k] = sppf[warp][(2 * mt) * 8 + r][k];
            pB[mt][k] = sppf[warp][(2 * mt + 1) * 8 + r][k];
        }

    const int tb = (cc << 3);             // A-table perm base for this cc
    const int jbl = (jb8 >> 3) * 256;     // B-table coalesced block base

    // ---- layer0: X1 = relu(A1[i] + B1[j] + ppf@W1p)  (scalar fp32 ppf GEMM) ----
    float cx[2][4][4];
#pragma unroll
    for (int c4 = 0; c4 < 2; c4++) {
        // coalesced B row (j = jb8 + r, perm cols for this cc): 512B/warp contiguous
        float4 bv = *(const float4*)(g_B1 + jbl + c4 * 128 + lane * 4);
#pragma unroll
        for (int mt = 0; mt < 2; mt++) {
            float4 ar = ((const float4*)(g_A1 + ((ib + 2 * mt) << 5) + tb))[c4];
            float4 as = ((const float4*)(g_A1 + ((ib + 2 * mt + 1) << 5) + tb))[c4];
#pragma unroll
            for (int h = 0; h < 2; h++) {
                int nt = 2 * c4 + h;
                int col = 8 * nt + col0;
                float bxv = h ? bv.z : bv.x, byv = h ? bv.w : bv.y;
                float arx = h ? ar.z : ar.x, ary = h ? ar.w : ar.y;
                float asx = h ? as.z : as.x, asy = h ? as.w : as.y;
                float c0 = arx + bxv, c1 = ary + byv;
                float c2 = asx + bxv, c3 = asy + byv;
#pragma unroll
                for (int k = 0; k < 4; k++) {
                    float2 wv = *(const float2*)&sW1p[k][col];
                    c0 = fmaf(pA[mt][k], wv.x, c0); c1 = fmaf(pA[mt][k], wv.y, c1);
                    c2 = fmaf(pB[mt][k], wv.x, c2); c3 = fmaf(pB[mt][k], wv.y, c3);
                }
                cx[mt][nt][0] = c0; cx[mt][nt][1] = c1;
                cx[mt][nt][2] = c2; cx[mt][nt][3] = c3;
            }
        }
    }
    // X1 hi-only (post-relu hidden, single consumer)
    u32 x1h[2][2][4];
#pragma unroll
    for (int mt = 0; mt < 2; mt++)
#pragma unroll
        for (int kt = 0; kt < 2; kt++)
            d2a_h<true>(cx[mt][2 * kt], cx[mt][2 * kt + 1], x1h[mt][kt]);

    // ---- residual R0 = A0[i] + B0[j] + ppf@W0p  (reuse cx) ----
#pragma unroll
    for (int c4 = 0; c4 < 2; c4++) {
        float4 bv = *(const float4*)(g_B0 + jbl + c4 * 128 + lane * 4);
#pragma unroll
        for (int mt = 0; mt < 2; mt++) {
            float4 ar = ((const float4*)(g_A0 + ((ib + 2 * mt) << 5) + tb))[c4];
            float4 as = ((const float4*)(g_A0 + ((ib + 2 * mt + 1) << 5) + tb))[c4];
#pragma unroll
            for (int h = 0; h < 2; h++) {
                int nt = 2 * c4 + h;
                int col = 8 * nt + col0;
                float bxv = h ? bv.z : bv.x, byv = h ? bv.w : bv.y;
                float arx = h ? ar.z : ar.x, ary = h ? ar.w : ar.y;
                float asx = h ? as.z : as.x, asy = h ? as.w : as.y;
                float c0 = arx + bxv, c1 = ary + byv;
                float c2 = asx + bxv, c3 = asy + byv;
#pragma unroll
                for (int k = 0; k < 4; k++) {
                    float2 wv = *(const float2*)&sW0p[k][col];
                    c0 = fmaf(pA[mt][k], wv.x, c0); c1 = fmaf(pA[mt][k], wv.y, c1);
                    c2 = fmaf(pB[mt][k], wv.x, c2); c3 = fmaf(pB[mt][k], wv.y, c3);
                }
                cx[mt][nt][0] = c0; cx[mt][nt][1] = c1;
                cx[mt][nt][2] = c2; cx[mt][nt][3] = c3;
            }
        }
    }

    // ---- l0fc2: X2 = X1@W2 + b2 + R0  (hi-only A) ----
#pragma unroll
    for (int nt = 0; nt < 4; nt++) {
        float2 bv = *(const float2*)(l0b2 + 8 * nt + col0);
#pragma unroll
        for (int mt = 0; mt < 2; mt++) {
            cx[mt][nt][0] += bv.x; cx[mt][nt][1] += bv.y;
            cx[mt][nt][2] += bv.x; cx[mt][nt][3] += bv.y;
        }
    }
#pragma unroll
    for (int kt = 0; kt < 2; kt++)
#pragma unroll
        for (int nt = 0; nt < 4; nt++) {
            u64 wv = g_frag[(T_L0W2 + kt * 4 + nt) * 32 + lane];
            mma_acc(cx[0][nt], x1h[0][kt], wv);
            mma_acc(cx[1][nt], x1h[1][kt], wv);
        }
    u32 x2h[2][2][4], x2l[2][2][4];
#pragma unroll
    for (int mt = 0; mt < 2; mt++)
#pragma unroll
        for (int kt = 0; kt < 2; kt++)
            d2a<false>(cx[mt][2 * kt], cx[mt][2 * kt + 1], x2h[mt][kt], x2l[mt][kt]);

    // ---- layer1 fc1: H = relu(X2@W1 + b1) -- accumulate in cx ----
#pragma unroll
    for (int nt = 0; nt < 4; nt++) {
        float2 bv = *(const float2*)(l1b1 + 8 * nt + col0);
#pragma unroll
        for (int mt = 0; mt < 2; mt++) {
            cx[mt][nt][0] = bv.x; cx[mt][nt][1] = bv.y;
            cx[mt][nt][2] = bv.x; cx[mt][nt][3] = bv.y;
        }
    }
#pragma unroll
    for (int kt = 0; kt < 2; kt++)
#pragma unroll
        for (int nt = 0; nt < 4; nt++) {
            u64 wv = g_frag[(T_L1W1 + kt * 4 + nt) * 32 + lane];
            mma2(cx[0][nt], x2h[0][kt], x2l[0][kt], wv);
            mma2(cx[1][nt], x2h[1][kt], x2l[1][kt], wv);
        }
    u32 hh[2][2][4];
#pragma unroll
    for (int mt = 0; mt < 2; mt++)
#pragma unroll
        for (int kt = 0; kt < 2; kt++)
            d2a_h<true>(cx[mt][2 * kt], cx[mt][2 * kt + 1], hh[mt][kt]);

    // ---- layer1 fc2: X3 = H@W2 + b2 + X2 (X2 reconstructed from x2h + x2l) ----
#pragma unroll
    for (int kt = 0; kt < 2; kt++)
#pragma unroll
        for (int h = 0; h < 2; h++) {
            int nt = 2 * kt + h;
            float2 bv = *(const float2*)(l1b2 + 8 * nt + col0);
#pragma unroll
            for (int mt = 0; mt < 2; mt++) {
                float2 hA = h2f(x2h[mt][kt][2 * h]),     lA = h2f(x2l[mt][kt][2 * h]);
                float2 hB = h2f(x2h[mt][kt][2 * h + 1]), lB = h2f(x2l[mt][kt][2 * h + 1]);
                cx[mt][nt][0] = bv.x + hA.x + lA.x;
                cx[mt][nt][1] = bv.y + hA.y + lA.y;
                cx[mt][nt][2] = bv.x + hB.x + lB.x;
                cx[mt][nt][3] = bv.y + hB.y + lB.y;
            }
        }
#pragma unroll
    for (int kt = 0; kt < 2; kt++)
#pragma unroll
        for (int nt = 0; nt < 4; nt++) {
            u64 wv = g_frag[(T_L1W2 + kt * 4 + nt) * 32 + lane];
            mma_acc(cx[0][nt], hh[0][kt], wv);
            mma_acc(cx[1][nt], hh[1][kt], wv);
        }
    // X3 hi-only (consumed only as A operand of l2fc0/l2fc1)
    u32 x3h[2][2][4];
#pragma unroll
    for (int mt = 0; mt < 2; mt++)
#pragma unroll
        for (int kt = 0; kt < 2; kt++)
            d2a_h<false>(cx[mt][2 * kt], cx[mt][2 * kt + 1], x3h[mt][kt]);

    // ---- layer2 ----
    float ca[2][2][4], cb[2][2][4];
#pragma unroll
    for (int nt = 0; nt < 2; nt++) {
        float2 b0v = *(const float2*)(l2b0 + 8 * nt + col0);
        float2 b1v = *(const float2*)(l2b1 + 8 * nt + col0);
#pragma unroll
        for (int mt = 0; mt < 2; mt++) {
            ca[mt][nt][0] = b0v.x; ca[mt][nt][1] = b0v.y;
            ca[mt][nt][2] = b0v.x; ca[mt][nt][3] = b0v.y;
            cb[mt][nt][0] = b1v.x; cb[mt][nt][1] = b1v.y;
            cb[mt][nt][2] = b1v.x; cb[mt][nt][3] = b1v.y;
        }
    }
#pragma unroll
    for (int kt = 0; kt < 2; kt++)
#pragma unroll
        for (int nt = 0; nt < 2; nt++) {
            u64 w0v = g_frag[(T_L2W0 + kt * 2 + nt) * 32 + lane];
            u64 w1v = g_frag[(T_L2W1 + kt * 2 + nt) * 32 + lane];
#pragma unroll
            for (int mt = 0; mt < 2; mt++) {
                mma_acc(ca[mt][nt], x3h[mt][kt], w0v);
                mma_acc(cb[mt][nt], x3h[mt][kt], w1v);
            }
        }
    u32 h2h[2][4];
#pragma unroll
    for (int mt = 0; mt < 2; mt++) d2a_h<true>(cb[mt][0], cb[mt][1], h2h[mt]);
#pragma unroll
    for (int nt = 0; nt < 2; nt++) {
        float2 bv = *(const float2*)(l2b2 + 8 * nt + col0);
        u64 wv = g_frag[(T_L2W2 + nt) * 32 + lane];
#pragma unroll
        for (int mt = 0; mt < 2; mt++) {
            ca[mt][nt][0] += bv.x; ca[mt][nt][1] += bv.y;
            ca[mt][nt][2] += bv.x; ca[mt][nt][3] += bv.y;
            mma_acc(ca[mt][nt], h2h[mt], wv);
        }
    }
    // X4 hi-only
    u32 x4h[2][4];
#pragma unroll
    for (int mt = 0; mt < 2; mt++) d2a_h<false>(ca[mt][0], ca[mt][1], x4h[mt]);

    // ---- final: OUT = X4 @ fw + fb -> stage in smem (row s = i_loc*8 + j_loc) ----
#pragma unroll
    for (int nt = 0; nt < 9; nt++) {
        int col = 8 * nt + col0;
        bool valid = (col < 66);
        float2 bv = valid ? *(const float2*)(fb + col) : make_float2(0.f, 0.f);
        u64 wv = g_frag[(T_FW + nt) * 32 + lane];
#pragma unroll
        for (int mt = 0; mt < 2; mt++) {
            float cf[4] = {bv.x, bv.y, bv.x, bv.y};
            mma_acc(cf, x4h[mt], wv);
            *(float2*)&sout[warp][(2 * mt) * 8 + r][col]     = make_float2(cf[0], cf[1]);
            *(float2*)&sout[warp][(2 * mt + 1) * 8 + r][col] = make_float2(cf[2], cf[3]);
        }
    }
    __syncwarp();
    // dense copy, division-free: per i-block, 8 full-width float2 rows + 8-lane tail
    {
        const float* src = &sout[warp][0][0];
#pragma unroll
        for (int blk = 0; blk < 4; blk++) {
            float* dst = out + (((size_t)(ib + blk) << 10) + (size_t)jb8) * 66ull;
#pragma unroll
            for (int row = 0; row < 8; row++) {
                float2 v = *(const float2*)(src + (blk * 8 + row) * SOUT_STRIDE + 2 * lane);
                *(float2*)(dst + row * 66 + 2 * lane) = v;
            }
            if (lane < 8) {
                float2 v = *(const float2*)(src + (blk * 8 + lane) * SOUT_STRIDE + 64);
                *(float2*)(dst + lane * 66 + 64) = v;
            }
        }
    }
}

extern "C" void kernel_launch(void* const* d_in, const int* in_sizes, int n_in,
                              void* d_out, int out_size) {
    const float* pc   = (const float*)d_in[0];
    const float* nrm  = (const float*)d_in[1];
    const float* dist = (const float*)d_in[2];
    const float* feat = (const float*)d_in[3];
    const float* w0   = (const float*)d_in[4];   const float* b0   = (const float*)d_in[5];
    const float* w1   = (const float*)d_in[6];   const float* b1   = (const float*)d_in[7];
    const float* l0w2 = (const float*)d_in[8];   const float* l0b2 = (const float*)d_in[9];
    const float* l1w1 = (const float*)d_in[10];  const float* l1b1 = (const float*)d_in[11];
    const float* l1w2 = (const float*)d_in[12];  const float* l1b2 = (const float*)d_in[13];
    const float* l2w0 = (const float*)d_in[14];  const float* l2b0 = (const float*)d_in[15];
    const float* l2w1 = (const float*)d_in[16];  const float* l2b1 = (const float*)d_in[17];
    const float* l2w2 = (const float*)d_in[18];  const float* l2b2 = (const float*)d_in[19];
    const float* fw   = (const float*)d_in[20];  const float* fb   = (const float*)d_in[21];
    float* out = (float*)d_out;

    prep<<<267, 256>>>(feat, w0, b0, w1, b1,
                       l0w2, l1w1, l1w2, l2w0, l2w1, l2w2, fw);
    ppf_main<<<8192, 128>>>(pc, nrm, dist, w0, w1,
                            l0b2, l1b1, l1b2, l2b0, l2b1, l2b2, fb, out);
}

// round 15
// speedup vs baseline: 1.1876x; 1.0273x over previous
#include <cuda_runtime.h>
#include <cuda_fp16.h>
#include <cstdint>

typedef unsigned long long u64;
typedef unsigned u32;

// ===== per-point separable layer0 tables =====
// A tables: PERMUTED per-point: index point*32 + cc*8 + nt*2 + e  (c = 8nt+2cc+e)
// B tables: warp-coalesced: [jblock=j>>3][c4][(j&7)*4+cc][q]  (perm p = cc*8+c4*4+q)
__device__ float g_A0[1024 * 32];
__device__ float g_B0[1024 * 32];
__device__ float g_A1[1024 * 32];
__device__ float g_B1[1024 * 32];

// ================= weight B-fragments (single fp16) =================
// Tile-PAIR interleaved: tile t lives at g_frag[(t>>1)*64 + lane*2 + (t&1)]
// so a ulonglong2 load at [(t>>1)*32 + lane] yields tiles (2P, 2P+1).
#define T_L0W2  0    // 2kt x 4nt
#define T_L1W1  8
#define T_L1W2  16
#define T_L2W0  24   // 2kt x 2nt
#define T_L2W1  28
#define T_L2W2  32   // 1kt x 2nt
#define T_FW    34   // 1kt x 9nt (N=66 pad 72)
#define N_TILES 44   // 43 real + 1 zero pad (tile 43)

__device__ __align__(16) u64 g_frag[N_TILES * 32];

__device__ __forceinline__ u32 h16b(float v) {
    return (u32)__half_as_ushort(__float2half_rn(v));
}

// ---- fused prep: blocks [0,256) = per-point tables; blocks [256,262) = frags ----
__global__ void prep(const float* __restrict__ feat,
                     const float* __restrict__ w0, const float* __restrict__ b0,
                     const float* __restrict__ w1, const float* __restrict__ b1,
                     const float* __restrict__ l0w2, const float* __restrict__ l1w1,
                     const float* __restrict__ l1w2, const float* __restrict__ l2w0,
                     const float* __restrict__ l2w1, const float* __restrict__ l2w2,
                     const float* __restrict__ fw) {
    int b = blockIdx.x;
    if (b < 256) {
        int t = b * 256 + threadIdx.x;          // 65536 threads
        int i = t >> 6, rem = t & 63, sel = rem >> 5, c = rem & 31;
        const float* f = feat + i * 40;
        const float* w = sel ? w1 : w0;
        float a = sel ? b1[c] : b0[c], bo = 0.f;
#pragma unroll
        for (int k = 0; k < 40; k++) {
            float fv = f[k];
            a  = fmaf(fv, w[k * 32 + c],        a);
            bo = fmaf(fv, w[(k + 40) * 32 + c], bo);
        }
        // permuted index: c = 8*nt + 2*cc + e  ->  p = cc*8 + nt*2 + e
        int p = ((c & 7) >> 1) * 8 + (c >> 3) * 2 + (c & 1);
        // B-table coalesced index
        int jblock = i >> 3, rr = i & 7;
        int ccp = p >> 3, c4p = (p >> 2) & 1, q = p & 3;
        int nb = jblock * 256 + c4p * 128 + (rr * 4 + ccp) * 4 + q;
        if (sel) { g_A1[i * 32 + p] = a; g_B1[nb] = bo; }
        else     { g_A0[i * 32 + p] = a; g_B0[nb] = bo; }
    } else {
        int e = (b - 256) * 256 + threadIdx.x;
        if (e >= N_TILES * 32) return;
        struct Spec { const float* w; int K, N, nnt, base, ntiles; };
        Spec sp[7] = {
            {l0w2, 32, 32, 4, T_L0W2, 8},
            {l1w1, 32, 32, 4, T_L1W1, 8},
            {l1w2, 32, 32, 4, T_L1W2, 8},
            {l2w0, 32, 16, 2, T_L2W0, 4},
            {l2w1, 32, 16, 2, T_L2W1, 4},
            {l2w2, 16, 16, 2, T_L2W2, 2},
            {fw,   16, 66, 9, T_FW,   9},
        };
        int tile = e >> 5, lane = e & 31;
        int si = -1;
        for (int q = 0; q < 7; q++)
            if (tile >= sp[q].base && tile < sp[q].base + sp[q].ntiles) si = q;
        u64 val = 0ull;
        if (si >= 0) {
            const float* w = sp[si].w;
            int K = sp[si].K, N = sp[si].N, nnt = sp[si].nnt;
            int lt = tile - sp[si].base, kt = lt / nnt, nt = lt % nnt;
            int n = nt * 8 + (lane >> 2), cc = lane & 3;
            int ks[4] = {kt * 16 + 2 * cc, kt * 16 + 2 * cc + 1,
                         kt * 16 + 2 * cc + 8, kt * 16 + 2 * cc + 9};
            u32 bits[4];
#pragma unroll
            for (int q = 0; q < 4; q++) {
                int k = ks[q];
                float v = (k < K && n < N) ? w[k * N + n] : 0.f;
                bits[q] = h16b(v);
            }
            u32 lo = (bits[1] << 16) | bits[0];
            u32 hi = (bits[3] << 16) | bits[2];
            val = ((u64)hi << 32) | (u64)lo;
        }
        // pair-interleaved store
        g_frag[(tile >> 1) * 64 + lane * 2 + (tile & 1)] = val;
    }
}

// ================= MMA helpers (fp16 in, fp32 acc) =================
__device__ __forceinline__ void mma_acc(float c[4], const u32 a[4], u64 b) {
    u32 b0 = (u32)b, b1 = (u32)(b >> 32);
    asm volatile("mma.sync.aligned.m16n8k16.row.col.f32.f16.f16.f32 "
        "{%0,%1,%2,%3}, {%4,%5,%6,%7}, {%8,%9}, {%0,%1,%2,%3};"
        : "+f"(c[0]), "+f"(c[1]), "+f"(c[2]), "+f"(c[3])
        : "r"(a[0]), "r"(a[1]), "r"(a[2]), "r"(a[3]), "r"(b0), "r"(b1));
}

// pair load: tiles (2P, 2P+1)
__device__ __forceinline__ ulonglong2 frag_pair(int P, int lane) {
    return ((const ulonglong2*)g_frag)[P * 32 + lane];
}

// pack (x0 low, x1 high) into fp16x2 hi, residue into lo
__device__ __forceinline__ void split2(float x0, float x1, u32& hi, u32& lo) {
    __half2 h = __floats2half2_rn(x0, x1);
    float2 f = __half22float2(h);
    __half2 l = __floats2half2_rn(x0 - f.x, x1 - f.y);
    hi = *reinterpret_cast<u32*>(&h);
    lo = *reinterpret_cast<u32*>(&l);
}
__device__ __forceinline__ u32 split2h(float x0, float x1) {
    __half2 h = __floats2half2_rn(x0, x1);
    return *reinterpret_cast<u32*>(&h);
}
__device__ __forceinline__ float2 h2f(u32 v) {
    __half2 h = *reinterpret_cast<__half2*>(&v);
    return __half22float2(h);
}

// D tiles (ntile 2kt, 2kt+1) -> A frag (ktile kt), hi+lo, optional relu
template<bool RELU>
__device__ __forceinline__ void d2a(const float* d0, const float* d1, u32* ah, u32* al) {
    float v0 = d0[0], v1 = d0[1], v2 = d0[2], v3 = d0[3];
    float w0 = d1[0], w1 = d1[1], w2 = d1[2], w3 = d1[3];
    if (RELU) {
        v0 = fmaxf(v0, 0.f); v1 = fmaxf(v1, 0.f); v2 = fmaxf(v2, 0.f); v3 = fmaxf(v3, 0.f);
        w0 = fmaxf(w0, 0.f); w1 = fmaxf(w1, 0.f); w2 = fmaxf(w2, 0.f); w3 = fmaxf(w3, 0.f);
    }
    split2(v0, v1, ah[0], al[0]);
    split2(v2, v3, ah[1], al[1]);
    split2(w0, w1, ah[2], al[2]);
    split2(w2, w3, ah[3], al[3]);
}
// hi-only A frag, optional relu
template<bool RELU>
__device__ __forceinline__ void d2a_h(const float* d0, const float* d1, u32* ah) {
    float v0 = d0[0], v1 = d0[1], v2 = d0[2], v3 = d0[3];
    float w0 = d1[0], w1 = d1[1], w2 = d1[2], w3 = d1[3];
    if (RELU) {
        v0 = fmaxf(v0, 0.f); v1 = fmaxf(v1, 0.f); v2 = fmaxf(v2, 0.f); v3 = fmaxf(v3, 0.f);
        w0 = fmaxf(w0, 0.f); w1 = fmaxf(w1, 0.f); w2 = fmaxf(w2, 0.f); w3 = fmaxf(w3, 0.f);
    }
    ah[0] = split2h(v0, v1);
    ah[1] = split2h(v2, v3);
    ah[2] = split2h(w0, w1);
    ah[3] = split2h(w2, w3);
}

#define SOUT_STRIDE 74   // 74 mod 32 = 10 -> conflict-free row stagger, float2-aligned

// ====== main kernel: warp = 32 pairs, tiled 4i x 8j (two m16 tiles of 2i x 8j) ======
__global__ void __launch_bounds__(128, 4) ppf_main(
    const float* __restrict__ pc, const float* __restrict__ nrm,
    const float* __restrict__ dist,
    const float* __restrict__ fc0w, const float* __restrict__ fc1w,
    const float* __restrict__ l0b2, const float* __restrict__ l1b1,
    const float* __restrict__ l1b2, const float* __restrict__ l2b0,
    const float* __restrict__ l2b1, const float* __restrict__ l2b2,
    const float* __restrict__ fb, float* __restrict__ out)
{
    __shared__ float sppf[4][32][4];
    __shared__ float sW1p[4][32];
    __shared__ float sW0p[4][32];
    __shared__ float sout[4][32][SOUT_STRIDE];
    const int tid = threadIdx.x;
    const int lane = tid & 31, warp = tid >> 5;
    const int bx = blockIdx.x;
    const int ib = (bx >> 5) << 2;                    // 4 i's per CTA
    const int jb8 = ((bx & 31) << 5) + (warp << 3);   // 8 j's per warp
    const int r = lane >> 2, cc = lane & 3;
    const int col0 = 2 * cc;

    // stage ppf-weight rows (80..83) of fc1/fc0
    if (tid < 128) {
        sW1p[tid >> 5][tid & 31] = fc1w[80 * 32 + tid];
        sW0p[tid >> 5][tid & 31] = fc0w[80 * 32 + tid];
    }

    // ---- PPF features: lane = i_loc*8 + j_loc ----
    {
        int i = ib + (lane >> 3);
        int j = jb8 + (lane & 7);
        float pcix = pc[3 * i], pciy = pc[3 * i + 1], pciz = pc[3 * i + 2];
        float nix = nrm[3 * i], niy = nrm[3 * i + 1], niz = nrm[3 * i + 2];
        float pcjx = pc[3 * j], pcjy = pc[3 * j + 1], pcjz = pc[3 * j + 2];
        float njx = nrm[3 * j], njy = nrm[3 * j + 1], njz = nrm[3 * j + 2];
        float dd = dist[(i << 10) + j];
        float inv = 1.0f / (dd + 1e-7f);
        float xx0 = pcix - pcjx, xx1 = pciy - pcjy, xx2 = pciz - pcjz;
        sppf[warp][lane][0] = (nix * xx0 + niy * xx1 + niz * xx2) * inv;
        sppf[warp][lane][1] = (njx * xx0 + njy * xx1 + njz * xx2) * inv;
        sppf[warp][lane][2] = nix * njx + niy * njy + niz * njz;
        sppf[warp][lane][3] = dd;
    }
    __syncthreads();

    // ppf rows this lane needs: pA -> row r (pair (ib+2mt, jb8+r)), pB -> row r+8
    float pA[2][4], pB[2][4];
#pragma unroll
    for (int mt = 0; mt < 2; mt++)
#pragma unroll
        for (int k = 0; k < 4; k++) {
            pA[mt][k] = sppf[warp][(2 * mt) * 8 + r][k];
            pB[mt][k] = sppf[warp][(2 * mt + 1) * 8 + r][k];
        }

    const int tb = (cc << 3);             // A-table perm base for this cc
    const int jbl = (jb8 >> 3) * 256;     // B-table coalesced block base

    // ---- layer0: X1 = relu(A1[i] + B1[j] + ppf@W1p)  (scalar fp32 ppf GEMM) ----
    float cx[2][4][4];
#pragma unroll
    for (int c4 = 0; c4 < 2; c4++) {
        float4 bv = *(const float4*)(g_B1 + jbl + c4 * 128 + lane * 4);
#pragma unroll
        for (int mt = 0; mt < 2; mt++) {
            float4 ar = ((const float4*)(g_A1 + ((ib + 2 * mt) << 5) + tb))[c4];
            float4 as = ((const float4*)(g_A1 + ((ib + 2 * mt + 1) << 5) + tb))[c4];
#pragma unroll
            for (int h = 0; h < 2; h++) {
                int nt = 2 * c4 + h;
                int col = 8 * nt + col0;
                float bxv = h ? bv.z : bv.x, byv = h ? bv.w : bv.y;
                float arx = h ? ar.z : ar.x, ary = h ? ar.w : ar.y;
                float asx = h ? as.z : as.x, asy = h ? as.w : as.y;
                float c0 = arx + bxv, c1 = ary + byv;
                float c2 = asx + bxv, c3 = asy + byv;
#pragma unroll
                for (int k = 0; k < 4; k++) {
                    float2 wv = *(const float2*)&sW1p[k][col];
                    c0 = fmaf(pA[mt][k], wv.x, c0); c1 = fmaf(pA[mt][k], wv.y, c1);
                    c2 = fmaf(pB[mt][k], wv.x, c2); c3 = fmaf(pB[mt][k], wv.y, c3);
                }
                cx[mt][nt][0] = c0; cx[mt][nt][1] = c1;
                cx[mt][nt][2] = c2; cx[mt][nt][3] = c3;
            }
        }
    }
    // X1 hi-only (post-relu hidden, single consumer)
    u32 x1h[2][2][4];
#pragma unroll
    for (int mt = 0; mt < 2; mt++)
#pragma unroll
        for (int kt = 0; kt < 2; kt++)
            d2a_h<true>(cx[mt][2 * kt], cx[mt][2 * kt + 1], x1h[mt][kt]);

    // ---- residual R0 = A0[i] + B0[j] + ppf@W0p  (reuse cx) ----
#pragma unroll
    for (int c4 = 0; c4 < 2; c4++) {
        float4 bv = *(const float4*)(g_B0 + jbl + c4 * 128 + lane * 4);
#pragma unroll
        for (int mt = 0; mt < 2; mt++) {
            float4 ar = ((const float4*)(g_A0 + ((ib + 2 * mt) << 5) + tb))[c4];
            float4 as = ((const float4*)(g_A0 + ((ib + 2 * mt + 1) << 5) + tb))[c4];
#pragma unroll
            for (int h = 0; h < 2; h++) {
                int nt = 2 * c4 + h;
                int col = 8 * nt + col0;
                float bxv = h ? bv.z : bv.x, byv = h ? bv.w : bv.y;
                float arx = h ? ar.z : ar.x, ary = h ? ar.w : ar.y;
                float asx = h ? as.z : as.x, asy = h ? as.w : as.y;
                float c0 = arx + bxv, c1 = ary + byv;
                float c2 = asx + bxv, c3 = asy + byv;
#pragma unroll
                for (int k = 0; k < 4; k++) {
                    float2 wv = *(const float2*)&sW0p[k][col];
                    c0 = fmaf(pA[mt][k], wv.x, c0); c1 = fmaf(pA[mt][k], wv.y, c1);
                    c2 = fmaf(pB[mt][k], wv.x, c2); c3 = fmaf(pB[mt][k], wv.y, c3);
                }
                cx[mt][nt][0] = c0; cx[mt][nt][1] = c1;
                cx[mt][nt][2] = c2; cx[mt][nt][3] = c3;
            }
        }
    }

    // ---- l0fc2: X2 = X1@W2 + b2 + R0  (hi-only A, paired frag loads) ----
#pragma unroll
    for (int nt = 0; nt < 4; nt++) {
        float2 bv = *(const float2*)(l0b2 + 8 * nt + col0);
#pragma unroll
        for (int mt = 0; mt < 2; mt++) {
            cx[mt][nt][0] += bv.x; cx[mt][nt][1] += bv.y;
            cx[mt][nt][2] += bv.x; cx[mt][nt][3] += bv.y;
        }
    }
#pragma unroll
    for (int kt = 0; kt < 2; kt++) {
        ulonglong2 wA = frag_pair(T_L0W2 / 2 + kt * 2 + 0, lane);
        ulonglong2 wB = frag_pair(T_L0W2 / 2 + kt * 2 + 1, lane);
        u64 wv4[4] = {wA.x, wA.y, wB.x, wB.y};
#pragma unroll
        for (int nt = 0; nt < 4; nt++) {
            mma_acc(cx[0][nt], x1h[0][kt], wv4[nt]);
            mma_acc(cx[1][nt], x1h[1][kt], wv4[nt]);
        }
    }
    u32 x2h[2][2][4], x2l[2][2][4];
#pragma unroll
    for (int mt = 0; mt < 2; mt++)
#pragma unroll
        for (int kt = 0; kt < 2; kt++)
            d2a<false>(cx[mt][2 * kt], cx[mt][2 * kt + 1], x2h[mt][kt], x2l[mt][kt]);

    // ---- layer1 fc1: H = relu(X2@W1 + b1) -- hi-only X2 input ----
#pragma unroll
    for (int nt = 0; nt < 4; nt++) {
        float2 bv = *(const float2*)(l1b1 + 8 * nt + col0);
#pragma unroll
        for (int mt = 0; mt < 2; mt++) {
            cx[mt][nt][0] = bv.x; cx[mt][nt][1] = bv.y;
            cx[mt][nt][2] = bv.x; cx[mt][nt][3] = bv.y;
        }
    }
#pragma unroll
    for (int kt = 0; kt < 2; kt++) {
        ulonglong2 wA = frag_pair(T_L1W1 / 2 + kt * 2 + 0, lane);
        ulonglong2 wB = frag_pair(T_L1W1 / 2 + kt * 2 + 1, lane);
        u64 wv4[4] = {wA.x, wA.y, wB.x, wB.y};
#pragma unroll
        for (int nt = 0; nt < 4; nt++) {
            mma_acc(cx[0][nt], x2h[0][kt], wv4[nt]);
            mma_acc(cx[1][nt], x2h[1][kt], wv4[nt]);
        }
    }
    u32 hh[2][2][4];
#pragma unroll
    for (int mt = 0; mt < 2; mt++)
#pragma unroll
        for (int kt = 0; kt < 2; kt++)
            d2a_h<true>(cx[mt][2 * kt], cx[mt][2 * kt + 1], hh[mt][kt]);

    // ---- layer1 fc2: X3 = H@W2 + b2 + X2 (X2 reconstructed from x2h + x2l) ----
#pragma unroll
    for (int kt = 0; kt < 2; kt++)
#pragma unroll
        for (int h = 0; h < 2; h++) {
            int nt = 2 * kt + h;
            float2 bv = *(const float2*)(l1b2 + 8 * nt + col0);
#pragma unroll
            for (int mt = 0; mt < 2; mt++) {
                float2 hA = h2f(x2h[mt][kt][2 * h]),     lA = h2f(x2l[mt][kt][2 * h]);
                float2 hB = h2f(x2h[mt][kt][2 * h + 1]), lB = h2f(x2l[mt][kt][2 * h + 1]);
                cx[mt][nt][0] = bv.x + hA.x + lA.x;
                cx[mt][nt][1] = bv.y + hA.y + lA.y;
                cx[mt][nt][2] = bv.x + hB.x + lB.x;
                cx[mt][nt][3] = bv.y + hB.y + lB.y;
            }
        }
#pragma unroll
    for (int kt = 0; kt < 2; kt++) {
        ulonglong2 wA = frag_pair(T_L1W2 / 2 + kt * 2 + 0, lane);
        ulonglong2 wB = frag_pair(T_L1W2 / 2 + kt * 2 + 1, lane);
        u64 wv4[4] = {wA.x, wA.y, wB.x, wB.y};
#pragma unroll
        for (int nt = 0; nt < 4; nt++) {
            mma_acc(cx[0][nt], hh[0][kt], wv4[nt]);
            mma_acc(cx[1][nt], hh[1][kt], wv4[nt]);
        }
    }
    // X3 hi-only (consumed only as A operand of l2fc0/l2fc1)
    u32 x3h[2][2][4];
#pragma unroll
    for (int mt = 0; mt < 2; mt++)
#pragma unroll
        for (int kt = 0; kt < 2; kt++)
            d2a_h<false>(cx[mt][2 * kt], cx[mt][2 * kt + 1], x3h[mt][kt]);

    // ---- layer2 ----
    float ca[2][2][4], cb[2][2][4];
#pragma unroll
    for (int nt = 0; nt < 2; nt++) {
        float2 b0v = *(const float2*)(l2b0 + 8 * nt + col0);
        float2 b1v = *(const float2*)(l2b1 + 8 * nt + col0);
#pragma unroll
        for (int mt = 0; mt < 2; mt++) {
            ca[mt][nt][0] = b0v.x; ca[mt][nt][1] = b0v.y;
            ca[mt][nt][2] = b0v.x; ca[mt][nt][3] = b0v.y;
            cb[mt][nt][0] = b1v.x; cb[mt][nt][1] = b1v.y;
            cb[mt][nt][2] = b1v.x; cb[mt][nt][3] = b1v.y;
        }
    }
#pragma unroll
    for (int kt = 0; kt < 2; kt++) {
        ulonglong2 w0p = frag_pair(T_L2W0 / 2 + kt, lane);
        ulonglong2 w1p = frag_pair(T_L2W1 / 2 + kt, lane);
        u64 w0v[2] = {w0p.x, w0p.y}, w1v[2] = {w1p.x, w1p.y};
#pragma unroll
        for (int nt = 0; nt < 2; nt++)
#pragma unroll
            for (int mt = 0; mt < 2; mt++) {
                mma_acc(ca[mt][nt], x3h[mt][kt], w0v[nt]);
                mma_acc(cb[mt][nt], x3h[mt][kt], w1v[nt]);
            }
    }
    u32 h2h[2][4];
#pragma unroll
    for (int mt = 0; mt < 2; mt++) d2a_h<true>(cb[mt][0], cb[mt][1], h2h[mt]);
    {
        ulonglong2 wp = frag_pair(T_L2W2 / 2, lane);
        u64 wv2[2] = {wp.x, wp.y};
#pragma unroll
        for (int nt = 0; nt < 2; nt++) {
            float2 bv = *(const float2*)(l2b2 + 8 * nt + col0);
#pragma unroll
            for (int mt = 0; mt < 2; mt++) {
                ca[mt][nt][0] += bv.x; ca[mt][nt][1] += bv.y;
                ca[mt][nt][2] += bv.x; ca[mt][nt][3] += bv.y;
                mma_acc(ca[mt][nt], h2h[mt], wv2[nt]);
            }
        }
    }
    // X4 hi-only
    u32 x4h[2][4];
#pragma unroll
    for (int mt = 0; mt < 2; mt++) d2a_h<false>(ca[mt][0], ca[mt][1], x4h[mt]);

    // ---- final: OUT = X4 @ fw + fb -> stage in smem (paired frag loads) ----
#pragma unroll
    for (int p = 0; p < 5; p++) {
        ulonglong2 wp = frag_pair(T_FW / 2 + p, lane);
        u64 wv2[2] = {wp.x, wp.y};
#pragma unroll
        for (int hh2 = 0; hh2 < 2; hh2++) {
            int nt = 2 * p + hh2;
            if (nt > 8) continue;
            int col = 8 * nt + col0;
            bool valid = (col < 66);
            float2 bv = valid ? *(const float2*)(fb + col) : make_float2(0.f, 0.f);
#pragma unroll
            for (int mt = 0; mt < 2; mt++) {
                float cf[4] = {bv.x, bv.y, bv.x, bv.y};
                mma_acc(cf, x4h[mt], wv2[hh2]);
                *(float2*)&sout[warp][(2 * mt) * 8 + r][col]     = make_float2(cf[0], cf[1]);
                *(float2*)&sout[warp][(2 * mt + 1) * 8 + r][col] = make_float2(cf[2], cf[3]);
            }
        }
    }
    __syncwarp();
    // dense copy, division-free: per i-block, 8 full-width float2 rows + 8-lane tail
    {
        const float* src = &sout[warp][0][0];
#pragma unroll
        for (int blk = 0; blk < 4; blk++) {
            float* dst = out + (((size_t)(ib + blk) << 10) + (size_t)jb8) * 66ull;
#pragma unroll
            for (int row = 0; row < 8; row++) {
                float2 v = *(const float2*)(src + (blk * 8 + row) * SOUT_STRIDE + 2 * lane);
                *(float2*)(dst + row * 66 + 2 * lane) = v;
            }
            if (lane < 8) {
                float2 v = *(const float2*)(src + (blk * 8 + lane) * SOUT_STRIDE + 64);
                *(float2*)(dst + lane * 66 + 64) = v;
            }
        }
    }
}

extern "C" void kernel_launch(void* const* d_in, const int* in_sizes, int n_in,
                              void* d_out, int out_size) {
    const float* pc   = (const float*)d_in[0];
    const float* nrm  = (const float*)d_in[1];
    const float* dist = (const float*)d_in[2];
    const float* feat = (const float*)d_in[3];
    const float* w0   = (const float*)d_in[4];   const float* b0   = (const float*)d_in[5];
    const float* w1   = (const float*)d_in[6];   const float* b1   = (const float*)d_in[7];
    const float* l0w2 = (const float*)d_in[8];   const float* l0b2 = (const float*)d_in[9];
    const float* l1w1 = (const float*)d_in[10];  const float* l1b1 = (const float*)d_in[11];
    const float* l1w2 = (const float*)d_in[12];  const float* l1b2 = (const float*)d_in[13];
    const float* l2w0 = (const float*)d_in[14];  const float* l2b0 = (const float*)d_in[15];
    const float* l2w1 = (const float*)d_in[16];  const float* l2b1 = (const float*)d_in[17];
    const float* l2w2 = (const float*)d_in[18];  const float* l2b2 = (const float*)d_in[19];
    const float* fw   = (const float*)d_in[20];  const float* fb   = (const float*)d_in[21];
    float* out = (float*)d_out;

    prep<<<262, 256>>>(feat, w0, b0, w1, b1,
                       l0w2, l1w1, l1w2, l2w0, l2w1, l2w2, fw);
    ppf_main<<<8192, 128>>>(pc, nrm, dist, w0, w1,
                            l0b2, l1b1, l1b2, l2b0, l2b1, l2b2, fb, out);
}

// round 16
// speedup vs baseline: 1.2081x; 1.0172x over previous
#include <cuda_runtime.h>
#include <cuda_fp16.h>
#include <cstdint>

typedef unsigned long long u64;
typedef unsigned u32;

// ===== per-point separable layer0 tables =====
__device__ float g_A0[1024 * 32];
__device__ float g_B0[1024 * 32];
__device__ float g_A1[1024 * 32];
__device__ float g_B1[1024 * 32];

// ================= weight B-fragments (single fp16), pair-interleaved =================
#define T_L0W2  0
#define T_L1W1  8
#define T_L1W2  16
#define T_L2W0  24
#define T_L2W1  28
#define T_L2W2  32
#define T_FW    34
#define N_TILES 44   // 43 real + 1 zero pad

__device__ __align__(16) u64 g_frag[N_TILES * 32];

__device__ __forceinline__ u32 h16b(float v) {
    return (u32)__half_as_ushort(__float2half_rn(v));
}

// ---- fused prep ----
__global__ void prep(const float* __restrict__ feat,
                     const float* __restrict__ w0, const float* __restrict__ b0,
                     const float* __restrict__ w1, const float* __restrict__ b1,
                     const float* __restrict__ l0w2, const float* __restrict__ l1w1,
                     const float* __restrict__ l1w2, const float* __restrict__ l2w0,
                     const float* __restrict__ l2w1, const float* __restrict__ l2w2,
                     const float* __restrict__ fw) {
    int b = blockIdx.x;
    if (b < 256) {
        int t = b * 256 + threadIdx.x;
        int i = t >> 6, rem = t & 63, sel = rem >> 5, c = rem & 31;
        const float* f = feat + i * 40;
        const float* w = sel ? w1 : w0;
        float a = sel ? b1[c] : b0[c], bo = 0.f;
#pragma unroll
        for (int k = 0; k < 40; k++) {
            float fv = f[k];
            a  = fmaf(fv, w[k * 32 + c],        a);
            bo = fmaf(fv, w[(k + 40) * 32 + c], bo);
        }
        int p = ((c & 7) >> 1) * 8 + (c >> 3) * 2 + (c & 1);
        int jblock = i >> 3, rr = i & 7;
        int ccp = p >> 3, c4p = (p >> 2) & 1, q = p & 3;
        int nb = jblock * 256 + c4p * 128 + (rr * 4 + ccp) * 4 + q;
        if (sel) { g_A1[i * 32 + p] = a; g_B1[nb] = bo; }
        else     { g_A0[i * 32 + p] = a; g_B0[nb] = bo; }
    } else {
        int e = (b - 256) * 256 + threadIdx.x;
        if (e >= N_TILES * 32) return;
        struct Spec { const float* w; int K, N, nnt, base, ntiles; };
        Spec sp[7] = {
            {l0w2, 32, 32, 4, T_L0W2, 8},
            {l1w1, 32, 32, 4, T_L1W1, 8},
            {l1w2, 32, 32, 4, T_L1W2, 8},
            {l2w0, 32, 16, 2, T_L2W0, 4},
            {l2w1, 32, 16, 2, T_L2W1, 4},
            {l2w2, 16, 16, 2, T_L2W2, 2},
            {fw,   16, 66, 9, T_FW,   9},
        };
        int tile = e >> 5, lane = e & 31;
        int si = -1;
        for (int q = 0; q < 7; q++)
            if (tile >= sp[q].base && tile < sp[q].base + sp[q].ntiles) si = q;
        u64 val = 0ull;
        if (si >= 0) {
            const float* w = sp[si].w;
            int K = sp[si].K, N = sp[si].N, nnt = sp[si].nnt;
            int lt = tile - sp[si].base, kt = lt / nnt, nt = lt % nnt;
            int n = nt * 8 + (lane >> 2), cc = lane & 3;
            int ks[4] = {kt * 16 + 2 * cc, kt * 16 + 2 * cc + 1,
                         kt * 16 + 2 * cc + 8, kt * 16 + 2 * cc + 9};
            u32 bits[4];
#pragma unroll
            for (int q = 0; q < 4; q++) {
                int k = ks[q];
                float v = (k < K && n < N) ? w[k * N + n] : 0.f;
                bits[q] = h16b(v);
            }
            u32 lo = (bits[1] << 16) | bits[0];
            u32 hi = (bits[3] << 16) | bits[2];
            val = ((u64)hi << 32) | (u64)lo;
        }
        g_frag[(tile >> 1) * 64 + lane * 2 + (tile & 1)] = val;
    }
}

// ================= MMA helpers =================
__device__ __forceinline__ void mma_acc(float c[4], const u32 a[4], u64 b) {
    u32 b0 = (u32)b, b1 = (u32)(b >> 32);
    asm volatile("mma.sync.aligned.m16n8k16.row.col.f32.f16.f16.f32 "
        "{%0,%1,%2,%3}, {%4,%5,%6,%7}, {%8,%9}, {%0,%1,%2,%3};"
        : "+f"(c[0]), "+f"(c[1]), "+f"(c[2]), "+f"(c[3])
        : "r"(a[0]), "r"(a[1]), "r"(a[2]), "r"(a[3]), "r"(b0), "r"(b1));
}
__device__ __forceinline__ ulonglong2 frag_pair(int P, int lane) {
    return ((const ulonglong2*)g_frag)[P * 32 + lane];
}
__device__ __forceinline__ void split2(float x0, float x1, u32& hi, u32& lo) {
    __half2 h = __floats2half2_rn(x0, x1);
    float2 f = __half22float2(h);
    __half2 l = __floats2half2_rn(x0 - f.x, x1 - f.y);
    hi = *reinterpret_cast<u32*>(&h);
    lo = *reinterpret_cast<u32*>(&l);
}
__device__ __forceinline__ u32 split2h(float x0, float x1) {
    __half2 h = __floats2half2_rn(x0, x1);
    return *reinterpret_cast<u32*>(&h);
}
__device__ __forceinline__ float2 h2f(u32 v) {
    __half2 h = *reinterpret_cast<__half2*>(&v);
    return __half22float2(h);
}
template<bool RELU>
__device__ __forceinline__ void d2a(const float* d0, const float* d1, u32* ah, u32* al) {
    float v0 = d0[0], v1 = d0[1], v2 = d0[2], v3 = d0[3];
    float w0 = d1[0], w1 = d1[1], w2 = d1[2], w3 = d1[3];
    if (RELU) {
        v0 = fmaxf(v0, 0.f); v1 = fmaxf(v1, 0.f); v2 = fmaxf(v2, 0.f); v3 = fmaxf(v3, 0.f);
        w0 = fmaxf(w0, 0.f); w1 = fmaxf(w1, 0.f); w2 = fmaxf(w2, 0.f); w3 = fmaxf(w3, 0.f);
    }
    split2(v0, v1, ah[0], al[0]);
    split2(v2, v3, ah[1], al[1]);
    split2(w0, w1, ah[2], al[2]);
    split2(w2, w3, ah[3], al[3]);
}
template<bool RELU>
__device__ __forceinline__ void d2a_h(const float* d0, const float* d1, u32* ah) {
    float v0 = d0[0], v1 = d0[1], v2 = d0[2], v3 = d0[3];
    float w0 = d1[0], w1 = d1[1], w2 = d1[2], w3 = d1[3];
    if (RELU) {
        v0 = fmaxf(v0, 0.f); v1 = fmaxf(v1, 0.f); v2 = fmaxf(v2, 0.f); v3 = fmaxf(v3, 0.f);
        w0 = fmaxf(w0, 0.f); w1 = fmaxf(w1, 0.f); w2 = fmaxf(w2, 0.f); w3 = fmaxf(w3, 0.f);
    }
    ah[0] = split2h(v0, v1);
    ah[1] = split2h(v2, v3);
    ah[2] = split2h(w0, w1);
    ah[3] = split2h(w2, w3);
}

// ====== main kernel: warp = 32 pairs, 4i x 8j; TMA bulk store for copy-out ======
__global__ void __launch_bounds__(128, 4) ppf_main(
    const float* __restrict__ pc, const float* __restrict__ nrm,
    const float* __restrict__ dist,
    const float* __restrict__ fc0w, const float* __restrict__ fc1w,
    const float* __restrict__ l0b2, const float* __restrict__ l1b1,
    const float* __restrict__ l1b2, const float* __restrict__ l2b0,
    const float* __restrict__ l2b1, const float* __restrict__ l2b2,
    const float* __restrict__ fb, float* __restrict__ out)
{
    __shared__ float sppf[4][32][4];
    __shared__ float sW1p[4][32];
    __shared__ float sW0p[4][32];
    __shared__ __align__(16) float soutP[4 * 2112];   // per warp: 4 blocks x 528 packed
    const int tid = threadIdx.x;
    const int lane = tid & 31, warp = tid >> 5;
    const int bx = blockIdx.x;
    const int ib = (bx >> 5) << 2;
    const int jb8 = ((bx & 31) << 5) + (warp << 3);
    const int r = lane >> 2, cc = lane & 3;
    const int col0 = 2 * cc;

    if (tid < 128) {
        sW1p[tid >> 5][tid & 31] = fc1w[80 * 32 + tid];
        sW0p[tid >> 5][tid & 31] = fc0w[80 * 32 + tid];
    }

    // ---- PPF features: lane = i_loc*8 + j_loc ----
    {
        int i = ib + (lane >> 3);
        int j = jb8 + (lane & 7);
        float pcix = pc[3 * i], pciy = pc[3 * i + 1], pciz = pc[3 * i + 2];
        float nix = nrm[3 * i], niy = nrm[3 * i + 1], niz = nrm[3 * i + 2];
        float pcjx = pc[3 * j], pcjy = pc[3 * j + 1], pcjz = pc[3 * j + 2];
        float njx = nrm[3 * j], njy = nrm[3 * j + 1], njz = nrm[3 * j + 2];
        float dd = dist[(i << 10) + j];
        float inv = 1.0f / (dd + 1e-7f);
        float xx0 = pcix - pcjx, xx1 = pciy - pcjy, xx2 = pciz - pcjz;
        sppf[warp][lane][0] = (nix * xx0 + niy * xx1 + niz * xx2) * inv;
        sppf[warp][lane][1] = (njx * xx0 + njy * xx1 + njz * xx2) * inv;
        sppf[warp][lane][2] = nix * njx + niy * njy + niz * njz;
        sppf[warp][lane][3] = dd;
    }
    __syncthreads();

    float pA[2][4], pB[2][4];
#pragma unroll
    for (int mt = 0; mt < 2; mt++)
#pragma unroll
        for (int k = 0; k < 4; k++) {
            pA[mt][k] = sppf[warp][(2 * mt) * 8 + r][k];
            pB[mt][k] = sppf[warp][(2 * mt + 1) * 8 + r][k];
        }

    const int tb = (cc << 3);
    const int jbl = (jb8 >> 3) * 256;

    // ---- layer0: X1 = relu(A1[i] + B1[j] + ppf@W1p) ----
    float cx[2][4][4];
#pragma unroll
    for (int c4 = 0; c4 < 2; c4++) {
        float4 bv = *(const float4*)(g_B1 + jbl + c4 * 128 + lane * 4);
#pragma unroll
        for (int mt = 0; mt < 2; mt++) {
            float4 ar = ((const float4*)(g_A1 + ((ib + 2 * mt) << 5) + tb))[c4];
            float4 as = ((const float4*)(g_A1 + ((ib + 2 * mt + 1) << 5) + tb))[c4];
#pragma unroll
            for (int h = 0; h < 2; h++) {
                int nt = 2 * c4 + h;
                int col = 8 * nt + col0;
                float bxv = h ? bv.z : bv.x, byv = h ? bv.w : bv.y;
                float arx = h ? ar.z : ar.x, ary = h ? ar.w : ar.y;
                float asx = h ? as.z : as.x, asy = h ? as.w : as.y;
                float c0 = arx + bxv, c1 = ary + byv;
                float c2 = asx + bxv, c3 = asy + byv;
#pragma unroll
                for (int k = 0; k < 4; k++) {
                    float2 wv = *(const float2*)&sW1p[k][col];
                    c0 = fmaf(pA[mt][k], wv.x, c0); c1 = fmaf(pA[mt][k], wv.y, c1);
                    c2 = fmaf(pB[mt][k], wv.x, c2); c3 = fmaf(pB[mt][k], wv.y, c3);
                }
                cx[mt][nt][0] = c0; cx[mt][nt][1] = c1;
                cx[mt][nt][2] = c2; cx[mt][nt][3] = c3;
            }
        }
    }
    u32 x1h[2][2][4];
#pragma unroll
    for (int mt = 0; mt < 2; mt++)
#pragma unroll
        for (int kt = 0; kt < 2; kt++)
            d2a_h<true>(cx[mt][2 * kt], cx[mt][2 * kt + 1], x1h[mt][kt]);

    // ---- residual R0 ----
#pragma unroll
    for (int c4 = 0; c4 < 2; c4++) {
        float4 bv = *(const float4*)(g_B0 + jbl + c4 * 128 + lane * 4);
#pragma unroll
        for (int mt = 0; mt < 2; mt++) {
            float4 ar = ((const float4*)(g_A0 + ((ib + 2 * mt) << 5) + tb))[c4];
            float4 as = ((const float4*)(g_A0 + ((ib + 2 * mt + 1) << 5) + tb))[c4];
#pragma unroll
            for (int h = 0; h < 2; h++) {
                int nt = 2 * c4 + h;
                int col = 8 * nt + col0;
                float bxv = h ? bv.z : bv.x, byv = h ? bv.w : bv.y;
                float arx = h ? ar.z : ar.x, ary = h ? ar.w : ar.y;
                float asx = h ? as.z : as.x, asy = h ? as.w : as.y;
                float c0 = arx + bxv, c1 = ary + byv;
                float c2 = asx + bxv, c3 = asy + byv;
#pragma unroll
                for (int k = 0; k < 4; k++) {
                    float2 wv = *(const float2*)&sW0p[k][col];
                    c0 = fmaf(pA[mt][k], wv.x, c0); c1 = fmaf(pA[mt][k], wv.y, c1);
                    c2 = fmaf(pB[mt][k], wv.x, c2); c3 = fmaf(pB[mt][k], wv.y, c3);
                }
                cx[mt][nt][0] = c0; cx[mt][nt][1] = c1;
                cx[mt][nt][2] = c2; cx[mt][nt][3] = c3;
            }
        }
    }

    // ---- l0fc2: X2 = X1@W2 + b2 + R0 ----
#pragma unroll
    for (int nt = 0; nt < 4; nt++) {
        float2 bv = *(const float2*)(l0b2 + 8 * nt + col0);
#pragma unroll
        for (int mt = 0; mt < 2; mt++) {
            cx[mt][nt][0] += bv.x; cx[mt][nt][1] += bv.y;
            cx[mt][nt][2] += bv.x; cx[mt][nt][3] += bv.y;
        }
    }
#pragma unroll
    for (int kt = 0; kt < 2; kt++) {
        ulonglong2 wA = frag_pair(T_L0W2 / 2 + kt * 2 + 0, lane);
        ulonglong2 wB = frag_pair(T_L0W2 / 2 + kt * 2 + 1, lane);
        u64 wv4[4] = {wA.x, wA.y, wB.x, wB.y};
#pragma unroll
        for (int nt = 0; nt < 4; nt++) {
            mma_acc(cx[0][nt], x1h[0][kt], wv4[nt]);
            mma_acc(cx[1][nt], x1h[1][kt], wv4[nt]);
        }
    }
    u32 x2h[2][2][4], x2l[2][2][4];
#pragma unroll
    for (int mt = 0; mt < 2; mt++)
#pragma unroll
        for (int kt = 0; kt < 2; kt++)
            d2a<false>(cx[mt][2 * kt], cx[mt][2 * kt + 1], x2h[mt][kt], x2l[mt][kt]);

    // ---- layer1 fc1: H = relu(X2@W1 + b1) (hi-only X2) ----
#pragma unroll
    for (int nt = 0; nt < 4; nt++) {
        float2 bv = *(const float2*)(l1b1 + 8 * nt + col0);
#pragma unroll
        for (int mt = 0; mt < 2; mt++) {
            cx[mt][nt][0] = bv.x; cx[mt][nt][1] = bv.y;
            cx[mt][nt][2] = bv.x; cx[mt][nt][3] = bv.y;
        }
    }
#pragma unroll
    for (int kt = 0; kt < 2; kt++) {
        ulonglong2 wA = frag_pair(T_L1W1 / 2 + kt * 2 + 0, lane);
        ulonglong2 wB = frag_pair(T_L1W1 / 2 + kt * 2 + 1, lane);
        u64 wv4[4] = {wA.x, wA.y, wB.x, wB.y};
#pragma unroll
        for (int nt = 0; nt < 4; nt++) {
            mma_acc(cx[0][nt], x2h[0][kt], wv4[nt]);
            mma_acc(cx[1][nt], x2h[1][kt], wv4[nt]);
        }
    }
    u32 hh[2][2][4];
#pragma unroll
    for (int mt = 0; mt < 2; mt++)
#pragma unroll
        for (int kt = 0; kt < 2; kt++)
            d2a_h<true>(cx[mt][2 * kt], cx[mt][2 * kt + 1], hh[mt][kt]);

    // ---- layer1 fc2: X3 = H@W2 + b2 + X2 ----
#pragma unroll
    for (int kt = 0; kt < 2; kt++)
#pragma unroll
        for (int h = 0; h < 2; h++) {
            int nt = 2 * kt + h;
            float2 bv = *(const float2*)(l1b2 + 8 * nt + col0);
#pragma unroll
            for (int mt = 0; mt < 2; mt++) {
                float2 hA = h2f(x2h[mt][kt][2 * h]),     lA = h2f(x2l[mt][kt][2 * h]);
                float2 hB = h2f(x2h[mt][kt][2 * h + 1]), lB = h2f(x2l[mt][kt][2 * h + 1]);
                cx[mt][nt][0] = bv.x + hA.x + lA.x;
                cx[mt][nt][1] = bv.y + hA.y + lA.y;
                cx[mt][nt][2] = bv.x + hB.x + lB.x;
                cx[mt][nt][3] = bv.y + hB.y + lB.y;
            }
        }
#pragma unroll
    for (int kt = 0; kt < 2; kt++) {
        ulonglong2 wA = frag_pair(T_L1W2 / 2 + kt * 2 + 0, lane);
        ulonglong2 wB = frag_pair(T_L1W2 / 2 + kt * 2 + 1, lane);
        u64 wv4[4] = {wA.x, wA.y, wB.x, wB.y};
#pragma unroll
        for (int nt = 0; nt < 4; nt++) {
            mma_acc(cx[0][nt], hh[0][kt], wv4[nt]);
            mma_acc(cx[1][nt], hh[1][kt], wv4[nt]);
        }
    }
    u32 x3h[2][2][4];
#pragma unroll
    for (int mt = 0; mt < 2; mt++)
#pragma unroll
        for (int kt = 0; kt < 2; kt++)
            d2a_h<false>(cx[mt][2 * kt], cx[mt][2 * kt + 1], x3h[mt][kt]);

    // ---- layer2 ----
    float ca[2][2][4], cb[2][2][4];
#pragma unroll
    for (int nt = 0; nt < 2; nt++) {
        float2 b0v = *(const float2*)(l2b0 + 8 * nt + col0);
        float2 b1v = *(const float2*)(l2b1 + 8 * nt + col0);
#pragma unroll
        for (int mt = 0; mt < 2; mt++) {
            ca[mt][nt][0] = b0v.x; ca[mt][nt][1] = b0v.y;
            ca[mt][nt][2] = b0v.x; ca[mt][nt][3] = b0v.y;
            cb[mt][nt][0] = b1v.x; cb[mt][nt][1] = b1v.y;
            cb[mt][nt][2] = b1v.x; cb[mt][nt][3] = b1v.y;
        }
    }
#pragma unroll
    for (int kt = 0; kt < 2; kt++) {
        ulonglong2 w0p = frag_pair(T_L2W0 / 2 + kt, lane);
        ulonglong2 w1p = frag_pair(T_L2W1 / 2 + kt, lane);
        u64 w0v[2] = {w0p.x, w0p.y}, w1v[2] = {w1p.x, w1p.y};
#pragma unroll
        for (int nt = 0; nt < 2; nt++)
#pragma unroll
            for (int mt = 0; mt < 2; mt++) {
                mma_acc(ca[mt][nt], x3h[mt][kt], w0v[nt]);
                mma_acc(cb[mt][nt], x3h[mt][kt], w1v[nt]);
            }
    }
    u32 h2h[2][4];
#pragma unroll
    for (int mt = 0; mt < 2; mt++) d2a_h<true>(cb[mt][0], cb[mt][1], h2h[mt]);
    {
        ulonglong2 wp = frag_pair(T_L2W2 / 2, lane);
        u64 wv2[2] = {wp.x, wp.y};
#pragma unroll
        for (int nt = 0; nt < 2; nt++) {
            float2 bv = *(const float2*)(l2b2 + 8 * nt + col0);
#pragma unroll
            for (int mt = 0; mt < 2; mt++) {
                ca[mt][nt][0] += bv.x; ca[mt][nt][1] += bv.y;
                ca[mt][nt][2] += bv.x; ca[mt][nt][3] += bv.y;
                mma_acc(ca[mt][nt], h2h[mt], wv2[nt]);
            }
        }
    }
    u32 x4h[2][4];
#pragma unroll
    for (int mt = 0; mt < 2; mt++) d2a_h<false>(ca[mt][0], ca[mt][1], x4h[mt]);

    // ---- final: OUT = X4 @ fw + fb -> packed output-shaped smem ----
    float* wbase = soutP + warp * 2112;   // [iloc][528] contiguous blocks
#pragma unroll
    for (int p = 0; p < 5; p++) {
        ulonglong2 wp = frag_pair(T_FW / 2 + p, lane);
        u64 wv2[2] = {wp.x, wp.y};
#pragma unroll
        for (int hh2 = 0; hh2 < 2; hh2++) {
            int nt = 2 * p + hh2;
            if (nt > 8) continue;
            int col = 8 * nt + col0;
            bool valid = (col < 66);
            float2 bv = valid ? *(const float2*)(fb + col) : make_float2(0.f, 0.f);
#pragma unroll
            for (int mt = 0; mt < 2; mt++) {
                float cf[4] = {bv.x, bv.y, bv.x, bv.y};
                mma_acc(cf, x4h[mt], wv2[hh2]);
                if (valid) {
                    *(float2*)(wbase + (2 * mt) * 528 + r * 66 + col)     = make_float2(cf[0], cf[1]);
                    *(float2*)(wbase + (2 * mt + 1) * 528 + r * 66 + col) = make_float2(cf[2], cf[3]);
                }
            }
        }
    }
    __syncwarp();

    // ---- TMA bulk copy: 4 blocks x 2112B, lanes 0-3 ----
    if (lane < 4) {
        asm volatile("fence.proxy.async.shared::cta;" ::: "memory");
        u32 saddr;
        {
            const float* sp2 = wbase + lane * 528;
            asm("{ .reg .u64 t; cvta.to.shared.u64 t, %1; cvt.u32.u64 %0, t; }"
                : "=r"(saddr) : "l"(sp2));
        }
        float* dst = out + (((size_t)(ib + lane) << 10) + (size_t)jb8) * 66ull;
        asm volatile("cp.async.bulk.global.shared::cta.bulk_group [%0], [%1], %2;"
                     :: "l"(dst), "r"(saddr), "r"(2112) : "memory");
        asm volatile("cp.async.bulk.commit_group;" ::: "memory");
        asm volatile("cp.async.bulk.wait_group 0;" ::: "memory");
    }
}

extern "C" void kernel_launch(void* const* d_in, const int* in_sizes, int n_in,
                              void* d_out, int out_size) {
    const float* pc   = (const float*)d_in[0];
    const float* nrm  = (const float*)d_in[1];
    const float* dist = (const float*)d_in[2];
    const float* feat = (const float*)d_in[3];
    const float* w0   = (const float*)d_in[4];   const float* b0   = (const float*)d_in[5];
    const float* w1   = (const float*)d_in[6];   const float* b1   = (const float*)d_in[7];
    const float* l0w2 = (const float*)d_in[8];   const float* l0b2 = (const float*)d_in[9];
    const float* l1w1 = (const float*)d_in[10];  const float* l1b1 = (const float*)d_in[11];
    const float* l1w2 = (const float*)d_in[12];  const float* l1b2 = (const float*)d_in[13];
    const float* l2w0 = (const float*)d_in[14];  const float* l2b0 = (const float*)d_in[15];
    const float* l2w1 = (const float*)d_in[16];  const float* l2b1 = (const float*)d_in[17];
    const float* l2w2 = (const float*)d_in[18];  const float* l2b2 = (const float*)d_in[19];
    const float* fw   = (const float*)d_in[20];  const float* fb   = (const float*)d_in[21];
    float* out = (float*)d_out;

    prep<<<262, 256>>>(feat, w0, b0, w1, b1,
                       l0w2, l1w1, l1w2, l2w0, l2w1, l2w2, fw);
    ppf_main<<<8192, 128>>>(pc, nrm, dist, w0, w1,
                            l0b2, l1b1, l1b2, l2b0, l2b1, l2b2, fb, out);
}